// round 2
// baseline (speedup 1.0000x reference)
#include <cuda_runtime.h>
#include <math.h>
#include <stdint.h>

// ---------------- scratch buffers (device globals; no allocation allowed) ----
__device__ float g_x1[4ull*64*512*512];   // conv1 raw output
__device__ float g_x2[4ull*64*512*512];   // conv2 raw output
__device__ float g_dwt[4ull*256*256*256]; // DWT of relu(BN2(x2))
__device__ float g_y3[4ull*64*256*256];   // conv3 raw output
__device__ float g_sum[64];
__device__ float g_ss[64];
__device__ float g_a1[64], g_b1[64];
__device__ float g_a2[64], g_b2[64];
__device__ float g_a3[64], g_b3[64];

#define EPSV 1e-5f

// ---------------- zero stats ------------------------------------------------
__global__ void zero_stats_k(float* sum, float* ss) {
    int t = threadIdx.x;
    if (t < 64) { sum[t] = 0.f; ss[t] = 0.f; }
}

// ---------------- conv1: 3->64, 512x512 ------------------------------------
__global__ __launch_bounds__(256) void conv1_k(const float* __restrict__ in,
                                               const float* __restrict__ wg,
                                               const float* __restrict__ bias,
                                               float* __restrict__ out) {
    __shared__ float s_w[27][64];   // [ci*9+tap][co]
    int tid = threadIdx.x;
    for (int idx = tid; idx < 27 * 64; idx += 256) {
        int co = idx & 63;
        int t  = idx >> 6;
        s_w[t][co] = wg[co * 27 + t];
    }
    __syncthreads();

    size_t pid = (size_t)blockIdx.x * 256 + tid;   // over 4*512*512
    int w = (int)(pid & 511);
    int h = (int)((pid >> 9) & 511);
    int n = (int)(pid >> 18);

    const float* inp = in + (size_t)n * 3 * 512 * 512;
    float xv[27];
    int i = 0;
    #pragma unroll
    for (int ci = 0; ci < 3; ci++)
        #pragma unroll
        for (int kh = 0; kh < 3; kh++)
            #pragma unroll
            for (int kw = 0; kw < 3; kw++) {
                int hh = h + kh - 1, ww = w + kw - 1;
                xv[i++] = (hh >= 0 && hh < 512 && ww >= 0 && ww < 512)
                              ? __ldg(&inp[(size_t)ci * 512 * 512 + (size_t)hh * 512 + ww])
                              : 0.f;
            }

    size_t obase = ((size_t)n * 64) * (512 * 512) + (size_t)h * 512 + w;
    for (int co = 0; co < 64; co++) {
        float a = __ldg(&bias[co]);
        #pragma unroll
        for (int t = 0; t < 27; t++) a += xv[t] * s_w[t][co];
        out[obase + (size_t)co * 512 * 512] = a;
    }
}

// ---------------- generic tiled conv: C_IN -> 64 ----------------------------
// Tile: 8h x 32w x 64co per block, 256 threads, each thread 16co x 4px.
#define TH 8
#define TW 32
#define CIC 8

template <int C_IN, int H, int W, bool AFF>
__global__ __launch_bounds__(256, 2) void conv_k(const float* __restrict__ in,
                                                 const float* __restrict__ wg,
                                                 const float* __restrict__ bias,
                                                 const float* __restrict__ ain,
                                                 const float* __restrict__ bin,
                                                 float* __restrict__ out) {
    __shared__ float s_in[CIC][TH + 2][TW + 2];
    __shared__ float s_w[CIC][9][64];

    int n   = blockIdx.z;
    int th0 = blockIdx.y * TH;
    int tw0 = blockIdx.x * TW;
    int tid = threadIdx.x;
    int cg  = tid & 3;        // co group (16 co each)
    int pix = tid >> 2;       // 0..63
    int ph  = pix >> 3;       // 0..7
    int pw  = (pix & 7) * 4;  // 0..28

    float acc[16][4];
    #pragma unroll
    for (int k = 0; k < 16; k++)
        #pragma unroll
        for (int j = 0; j < 4; j++) acc[k][j] = 0.f;

    const float* in_n = in + (size_t)n * C_IN * H * W;

    for (int ci0 = 0; ci0 < C_IN; ci0 += CIC) {
        __syncthreads();
        // input tile (with halo); OOB -> 0 (zero padding happens AFTER affine)
        for (int idx = tid; idx < CIC * (TH + 2) * (TW + 2); idx += 256) {
            int ci  = idx / ((TH + 2) * (TW + 2));
            int rem = idx - ci * ((TH + 2) * (TW + 2));
            int r   = rem / (TW + 2);
            int c   = rem - r * (TW + 2);
            int gh  = th0 + r - 1;
            int gw  = tw0 + c - 1;
            float v = 0.f;
            if (gh >= 0 && gh < H && gw >= 0 && gw < W) {
                v = in_n[(size_t)(ci0 + ci) * H * W + (size_t)gh * W + gw];
                if (AFF) v = v * __ldg(&ain[ci0 + ci]) + __ldg(&bin[ci0 + ci]);
            }
            s_in[ci][r][c] = v;
        }
        // weights: s_w[ci][tap][co]
        for (int idx = tid; idx < CIC * 9 * 64; idx += 256) {
            int co = idx & 63;
            int t2 = idx >> 6;
            int tap = t2 % 9;
            int ci  = t2 / 9;
            s_w[ci][tap][co] = __ldg(&wg[((size_t)co * C_IN + ci0 + ci) * 9 + tap]);
        }
        __syncthreads();

        #pragma unroll 1
        for (int ci = 0; ci < CIC; ci++) {
            #pragma unroll
            for (int kh = 0; kh < 3; kh++) {
                float xr[6];
                #pragma unroll
                for (int t = 0; t < 6; t++) xr[t] = s_in[ci][ph + kh][pw + t];
                #pragma unroll
                for (int kw = 0; kw < 3; kw++) {
                    const float* wp = &s_w[ci][kh * 3 + kw][cg * 16];
                    #pragma unroll
                    for (int q = 0; q < 4; q++) {
                        float4 w4 = *(const float4*)(wp + 4 * q);
                        #pragma unroll
                        for (int j = 0; j < 4; j++) {
                            acc[q * 4 + 0][j] += xr[kw + j] * w4.x;
                            acc[q * 4 + 1][j] += xr[kw + j] * w4.y;
                            acc[q * 4 + 2][j] += xr[kw + j] * w4.z;
                            acc[q * 4 + 3][j] += xr[kw + j] * w4.w;
                        }
                    }
                }
            }
        }
    }

    float* op = out + ((size_t)n * 64) * H * W + (size_t)(th0 + ph) * W + (tw0 + pw);
    #pragma unroll
    for (int k = 0; k < 16; k++) {
        int co = cg * 16 + k;
        float bv = __ldg(&bias[co]);
        float4 v = make_float4(acc[k][0] + bv, acc[k][1] + bv,
                               acc[k][2] + bv, acc[k][3] + bv);
        *(float4*)(op + (size_t)co * H * W) = v;
    }
}

// ---------------- per-channel stats (sum, sumsq) ----------------------------
__global__ void stats_k(const float* __restrict__ x, int HW,
                        float* __restrict__ sum, float* __restrict__ ss) {
    int c = blockIdx.x;  // 0..63
    float s = 0.f, q = 0.f;
    int stride = gridDim.y * blockDim.x;
    int start  = blockIdx.y * blockDim.x + threadIdx.x;
    for (int n = 0; n < 4; n++) {
        const float* p = x + ((size_t)(n * 64 + c)) * HW;
        for (int i = start; i < HW; i += stride) {
            float v = p[i];
            s += v;
            q += v * v;
        }
    }
    #pragma unroll
    for (int o = 16; o > 0; o >>= 1) {
        s += __shfl_down_sync(0xffffffffu, s, o);
        q += __shfl_down_sync(0xffffffffu, q, o);
    }
    __shared__ float bs[8], bq[8];
    int lane = threadIdx.x & 31, wid = threadIdx.x >> 5;
    if (lane == 0) { bs[wid] = s; bq[wid] = q; }
    __syncthreads();
    if (threadIdx.x < 8) {
        s = bs[threadIdx.x];
        q = bq[threadIdx.x];
        #pragma unroll
        for (int o = 4; o > 0; o >>= 1) {
            s += __shfl_down_sync(0xffu, s, o);
            q += __shfl_down_sync(0xffu, q, o);
        }
        if (threadIdx.x == 0) {
            atomicAdd(&sum[c], s);
            atomicAdd(&ss[c], q);
        }
    }
}

__global__ void finalize_k(const float* __restrict__ g, const float* __restrict__ be,
                           float invM, const float* __restrict__ sum,
                           const float* __restrict__ ss,
                           float* __restrict__ a, float* __restrict__ b) {
    int c = threadIdx.x;
    if (c < 64) {
        float mean = sum[c] * invM;
        float var  = ss[c] * invM - mean * mean;
        float ai   = g[c] * rsqrtf(var + EPSV);
        a[c] = ai;
        b[c] = be[c] - mean * ai;
    }
}

// -------- BN2 affine + relu -> skip_con; Haar DWT -> g_dwt -------------------
// Each thread handles one (n,c,h2, w2-pair): covers a 2x4 input patch.
__global__ __launch_bounds__(256) void dwt_k(const float* __restrict__ x2,
                                             const float* __restrict__ a2,
                                             const float* __restrict__ b2,
                                             float* __restrict__ skip,
                                             float* __restrict__ dwt) {
    size_t idx = (size_t)blockIdx.x * 256 + threadIdx.x;  // < 4*64*256*128 = 2^23
    int wp = (int)(idx & 127);          // w2 pair -> w2 = 2*wp
    int h2 = (int)((idx >> 7) & 255);
    int c  = (int)((idx >> 15) & 63);
    int n  = (int)(idx >> 21);

    float a = __ldg(&a2[c]), b = __ldg(&b2[c]);
    size_t ibase = ((size_t)(n * 64 + c)) * 512 * 512 + (size_t)(2 * h2) * 512 + wp * 4;
    float4 r0 = *(const float4*)(x2 + ibase);
    float4 r1 = *(const float4*)(x2 + ibase + 512);
    r0.x = fmaxf(fmaf(r0.x, a, b), 0.f);
    r0.y = fmaxf(fmaf(r0.y, a, b), 0.f);
    r0.z = fmaxf(fmaf(r0.z, a, b), 0.f);
    r0.w = fmaxf(fmaf(r0.w, a, b), 0.f);
    r1.x = fmaxf(fmaf(r1.x, a, b), 0.f);
    r1.y = fmaxf(fmaf(r1.y, a, b), 0.f);
    r1.z = fmaxf(fmaf(r1.z, a, b), 0.f);
    r1.w = fmaxf(fmaf(r1.w, a, b), 0.f);

    *(float4*)(skip + ibase)       = r0;
    *(float4*)(skip + ibase + 512) = r1;

    // DWT: pixel0 uses (r0.x,r0.y,r1.x,r1.y); pixel1 uses (r0.z,r0.w,r1.z,r1.w)
    size_t dbase = ((size_t)(n * 256 + c)) * 256 * 256 + (size_t)h2 * 256 + wp * 2;
    const size_t CH = (size_t)64 * 256 * 256;

    float cA0 = (r0.x + r0.y + r1.x + r1.y) * 0.5f;
    float cH0 = (r0.x + r0.y - r1.x - r1.y) * 0.5f;
    float cV0 = (r0.x - r0.y + r1.x - r1.y) * 0.5f;
    float cD0 = (r0.x - r0.y - r1.x + r1.y) * 0.5f;
    float cA1 = (r0.z + r0.w + r1.z + r1.w) * 0.5f;
    float cH1 = (r0.z + r0.w - r1.z - r1.w) * 0.5f;
    float cV1 = (r0.z - r0.w + r1.z - r1.w) * 0.5f;
    float cD1 = (r0.z - r0.w - r1.z + r1.w) * 0.5f;

    *(float2*)(dwt + dbase)          = make_float2(cA0, cA1);
    *(float2*)(dwt + dbase + CH)     = make_float2(cH0, cH1);
    *(float2*)(dwt + dbase + 2 * CH) = make_float2(cV0, cV1);
    *(float2*)(dwt + dbase + 3 * CH) = make_float2(cD0, cD1);
}

// -------- BN3 affine + relu -> dwt_out --------------------------------------
__global__ __launch_bounds__(256) void bn3relu_k(const float* __restrict__ y3,
                                                 const float* __restrict__ a3,
                                                 const float* __restrict__ b3,
                                                 float* __restrict__ out) {
    size_t idx = (size_t)blockIdx.x * 256 + threadIdx.x;  // < 4*64*256*256 = 2^24
    int c = (int)((idx >> 16) & 63);
    float v = fmaf(y3[idx], __ldg(&a3[c]), __ldg(&b3[c]));
    out[idx] = fmaxf(v, 0.f);
}

// ---------------- host orchestration ----------------------------------------
extern "C" void kernel_launch(void* const* d_in, const int* in_sizes, int n_in,
                              void* d_out, int out_size) {
    const float* inp  = (const float*)d_in[0];
    const float* w1   = (const float*)d_in[1];
    const float* pb1  = (const float*)d_in[2];
    const float* pg1  = (const float*)d_in[3];
    const float* pbe1 = (const float*)d_in[4];
    const float* w2   = (const float*)d_in[5];
    const float* pb2  = (const float*)d_in[6];
    const float* pg2  = (const float*)d_in[7];
    const float* pbe2 = (const float*)d_in[8];
    const float* w3   = (const float*)d_in[9];
    const float* pb3  = (const float*)d_in[10];
    const float* pg3  = (const float*)d_in[11];
    const float* pbe3 = (const float*)d_in[12];

    float* out     = (float*)d_out;
    float* dwt_out = out;                        // 4*64*256*256
    float* skip    = out + 16777216ull;          // 4*64*512*512

    float *x1, *x2, *dwt, *y3, *sum, *ss;
    float *a1, *b1v, *a2, *b2v, *a3, *b3v;
    cudaGetSymbolAddress((void**)&x1,  g_x1);
    cudaGetSymbolAddress((void**)&x2,  g_x2);
    cudaGetSymbolAddress((void**)&dwt, g_dwt);
    cudaGetSymbolAddress((void**)&y3,  g_y3);
    cudaGetSymbolAddress((void**)&sum, g_sum);
    cudaGetSymbolAddress((void**)&ss,  g_ss);
    cudaGetSymbolAddress((void**)&a1,  g_a1);
    cudaGetSymbolAddress((void**)&b1v, g_b1);
    cudaGetSymbolAddress((void**)&a2,  g_a2);
    cudaGetSymbolAddress((void**)&b2v, g_b2);
    cudaGetSymbolAddress((void**)&a3,  g_a3);
    cudaGetSymbolAddress((void**)&b3v, g_b3);

    // conv1 -> x1 (raw)
    conv1_k<<<4096, 256>>>(inp, w1, pb1, x1);

    // BN1 stats -> affine (a1, b1)
    zero_stats_k<<<1, 64>>>(sum, ss);
    stats_k<<<dim3(64, 32), 256>>>(x1, 512 * 512, sum, ss);
    finalize_k<<<1, 64>>>(pg1, pbe1, 1.0f / (4.0f * 512 * 512), sum, ss, a1, b1v);

    // conv2(BN1(x1)) -> x2 (raw)
    conv_k<64, 512, 512, true><<<dim3(16, 64, 4), 256>>>(x1, w2, pb2, a1, b1v, x2);

    // BN2 stats -> affine (a2, b2)
    zero_stats_k<<<1, 64>>>(sum, ss);
    stats_k<<<dim3(64, 32), 256>>>(x2, 512 * 512, sum, ss);
    finalize_k<<<1, 64>>>(pg2, pbe2, 1.0f / (4.0f * 512 * 512), sum, ss, a2, b2v);

    // skip_con = relu(BN2(x2)); dwt = Haar(skip)
    dwt_k<<<32768, 256>>>(x2, a2, b2v, skip, dwt);

    // conv3(dwt) -> y3 (raw)
    conv_k<256, 256, 256, false><<<dim3(8, 32, 4), 256>>>(dwt, w3, pb3, nullptr, nullptr, y3);

    // BN3 stats -> affine (a3, b3)
    zero_stats_k<<<1, 64>>>(sum, ss);
    stats_k<<<dim3(64, 32), 256>>>(y3, 256 * 256, sum, ss);
    finalize_k<<<1, 64>>>(pg3, pbe3, 1.0f / (4.0f * 256 * 256), sum, ss, a3, b3v);

    // dwt_out = relu(BN3(y3))
    bn3relu_k<<<65536, 256>>>(y3, a3, b3v, dwt_out);
}

// round 3
// speedup vs baseline: 3.3596x; 3.3596x over previous
#include <cuda_runtime.h>
#include <math.h>
#include <stdint.h>

// ---------------- scratch buffers (device globals; no allocation allowed) ----
__device__ float g_x1[4ull*64*512*512];   // conv1 raw output
__device__ float g_x2[4ull*64*512*512];   // conv2 raw output
__device__ float g_dwt[4ull*256*256*256]; // DWT of relu(BN2(x2))
__device__ float g_y3[4ull*64*256*256];   // conv3 raw output
__device__ float g_sum[64];
__device__ float g_ss[64];
__device__ float g_a1[64], g_b1[64];
__device__ float g_a2[64], g_b2[64];
__device__ float g_a3[64], g_b3[64];

#define EPSV 1e-5f

__device__ __forceinline__ float to_tf32(float f) {
    uint32_t r;
    asm("cvt.rna.tf32.f32 %0, %1;" : "=r"(r) : "f"(f));
    return __uint_as_float(r);
}

// ---------------- zero stats ------------------------------------------------
__global__ void zero_stats_k(float* sum, float* ss) {
    int t = threadIdx.x;
    if (t < 64) { sum[t] = 0.f; ss[t] = 0.f; }
}

// ---------------- conv1: 3->64, 512x512 (bias dropped: BN cancels it) -------
__global__ __launch_bounds__(256) void conv1_k(const float* __restrict__ in,
                                               const float* __restrict__ wg,
                                               float* __restrict__ out) {
    __shared__ float s_w[27][64];   // [ci*9+tap][co]
    int tid = threadIdx.x;
    for (int idx = tid; idx < 27 * 64; idx += 256) {
        int co = idx & 63;
        int t  = idx >> 6;
        s_w[t][co] = wg[co * 27 + t];
    }
    __syncthreads();

    size_t pid = (size_t)blockIdx.x * 256 + tid;   // over 4*512*512
    int w = (int)(pid & 511);
    int h = (int)((pid >> 9) & 511);
    int n = (int)(pid >> 18);

    const float* inp = in + (size_t)n * 3 * 512 * 512;
    float xv[27];
    int i = 0;
    #pragma unroll
    for (int ci = 0; ci < 3; ci++)
        #pragma unroll
        for (int kh = 0; kh < 3; kh++)
            #pragma unroll
            for (int kw = 0; kw < 3; kw++) {
                int hh = h + kh - 1, ww = w + kw - 1;
                xv[i++] = (hh >= 0 && hh < 512 && ww >= 0 && ww < 512)
                              ? __ldg(&inp[(size_t)ci * 512 * 512 + (size_t)hh * 512 + ww])
                              : 0.f;
            }

    size_t obase = ((size_t)n * 64) * (512 * 512) + (size_t)h * 512 + w;
    for (int co = 0; co < 64; co++) {
        float a = 0.f;
        #pragma unroll
        for (int t = 0; t < 27; t++) a += xv[t] * s_w[t][co];
        out[obase + (size_t)co * 512 * 512] = a;
    }
}

// ---------------- tf32 mma implicit-GEMM conv: C_IN -> 64 -------------------
// Block: 64co x (8h x 32w) pixels, 256 threads = 8 warps.
// Warp: one h-row, 64co x 32w. mma.m16n8k8: 16co x 8pix per mma, k = 8 ci.
// K loop: ci chunks of 8, 9 taps each.
#define CI_STRIDE 344   // per-ci smem stride (>= 10*34, bank-conflict-free)

template <int C_IN, int H, int W, bool AFF>
__global__ __launch_bounds__(256) void convmma_k(const float* __restrict__ in,
                                                 const float* __restrict__ wg,
                                                 const float* __restrict__ ain,
                                                 const float* __restrict__ bin,
                                                 float* __restrict__ out) {
    __shared__ float s_in[8 * CI_STRIDE];          // [ci][10][34] padded
    __shared__ float s_wf[9 * 4 * 32 * 4];         // [tap][cog][lane][4] A-frag layout

    int n   = blockIdx.z;
    int th0 = blockIdx.y * 8;
    int tw0 = blockIdx.x * 32;
    int tid  = threadIdx.x;
    int warp = tid >> 5;
    int lane = tid & 31;
    int gid  = lane >> 2;   // 0..7
    int tig  = lane & 3;    // 0..3

    float c[4][4][4];       // [cog][pixfrag][c0..c3]
    #pragma unroll
    for (int a = 0; a < 4; a++)
        #pragma unroll
        for (int b = 0; b < 4; b++)
            #pragma unroll
            for (int d = 0; d < 4; d++) c[a][b][d] = 0.f;

    const float* in_n = in + (size_t)n * C_IN * H * W;

    for (int ci0 = 0; ci0 < C_IN; ci0 += 8) {
        __syncthreads();
        // ---- stage input tile (8ci x 10h x 34w, halo, affine, tf32) ----
        for (int idx = tid; idx < 8 * 340; idx += 256) {
            int ci  = idx / 340;
            int rem = idx - ci * 340;
            int r   = rem / 34;
            int col = rem - r * 34;
            int gh  = th0 + r - 1;
            int gw  = tw0 + col - 1;
            float v = 0.f;
            if (gh >= 0 && gh < H && gw >= 0 && gw < W) {
                v = in_n[(size_t)(ci0 + ci) * H * W + (size_t)gh * W + gw];
                if (AFF) v = fmaf(v, __ldg(&ain[ci0 + ci]), __ldg(&bin[ci0 + ci]));
            }
            s_in[ci * CI_STRIDE + r * 34 + col] = to_tf32(v);
        }
        // ---- stage weights in A-fragment layout ----
        for (int idx = tid; idx < 9 * 4 * 32 * 4; idx += 256) {
            int j   = idx & 3;
            int l   = (idx >> 2) & 31;
            int cog = (idx >> 7) & 3;
            int tap = idx >> 9;
            int co  = cog * 16 + (l >> 2) + ((j & 1) ? 8 : 0);
            int ci  = ci0 + (l & 3) + ((j & 2) ? 4 : 0);
            s_wf[idx] = to_tf32(__ldg(&wg[((size_t)co * C_IN + ci) * 9 + tap]));
        }
        __syncthreads();

        // ---- compute: 9 taps x 16 mmas ----
        #pragma unroll
        for (int kh = 0; kh < 3; kh++) {
            #pragma unroll
            for (int kw = 0; kw < 3; kw++) {
                int tap = kh * 3 + kw;
                uint32_t A[4][4];
                #pragma unroll
                for (int cog = 0; cog < 4; cog++) {
                    float4 a4 = *(const float4*)&s_wf[((tap * 4 + cog) * 32 + lane) * 4];
                    A[cog][0] = __float_as_uint(a4.x);
                    A[cog][1] = __float_as_uint(a4.y);
                    A[cog][2] = __float_as_uint(a4.z);
                    A[cog][3] = __float_as_uint(a4.w);
                }
                int rbase = (warp + kh) * 34;
                #pragma unroll
                for (int pf = 0; pf < 4; pf++) {
                    int col = pf * 8 + gid + kw;
                    uint32_t b0 = __float_as_uint(s_in[tig * CI_STRIDE + rbase + col]);
                    uint32_t b1 = __float_as_uint(s_in[(tig + 4) * CI_STRIDE + rbase + col]);
                    #pragma unroll
                    for (int cog = 0; cog < 4; cog++) {
                        asm volatile(
                            "mma.sync.aligned.m16n8k8.row.col.f32.tf32.tf32.f32 "
                            "{%0,%1,%2,%3}, {%4,%5,%6,%7}, {%8,%9}, {%0,%1,%2,%3};\n"
                            : "+f"(c[cog][pf][0]), "+f"(c[cog][pf][1]),
                              "+f"(c[cog][pf][2]), "+f"(c[cog][pf][3])
                            : "r"(A[cog][0]), "r"(A[cog][1]), "r"(A[cog][2]), "r"(A[cog][3]),
                              "r"(b0), "r"(b1));
                    }
                }
            }
        }
    }

    // ---- epilogue: no bias (BN cancels it) ----
    int h = th0 + warp;
    float* op = out + ((size_t)n * 64) * H * W + (size_t)h * W + tw0;
    #pragma unroll
    for (int cog = 0; cog < 4; cog++) {
        int co0 = cog * 16 + gid;
        #pragma unroll
        for (int pf = 0; pf < 4; pf++) {
            int w = pf * 8 + tig * 2;
            *(float2*)(op + (size_t)co0 * H * W + w) =
                make_float2(c[cog][pf][0], c[cog][pf][1]);
            *(float2*)(op + (size_t)(co0 + 8) * H * W + w) =
                make_float2(c[cog][pf][2], c[cog][pf][3]);
        }
    }
}

// ---------------- per-channel stats (sum, sumsq) ----------------------------
__global__ void stats_k(const float* __restrict__ x, int HW,
                        float* __restrict__ sum, float* __restrict__ ss) {
    int c = blockIdx.x;  // 0..63
    float s = 0.f, q = 0.f;
    int stride = gridDim.y * blockDim.x;
    int start  = blockIdx.y * blockDim.x + threadIdx.x;
    for (int n = 0; n < 4; n++) {
        const float* p = x + ((size_t)(n * 64 + c)) * HW;
        for (int i = start; i < HW; i += stride) {
            float v = p[i];
            s += v;
            q += v * v;
        }
    }
    #pragma unroll
    for (int o = 16; o > 0; o >>= 1) {
        s += __shfl_down_sync(0xffffffffu, s, o);
        q += __shfl_down_sync(0xffffffffu, q, o);
    }
    __shared__ float bs[8], bq[8];
    int lane = threadIdx.x & 31, wid = threadIdx.x >> 5;
    if (lane == 0) { bs[wid] = s; bq[wid] = q; }
    __syncthreads();
    if (threadIdx.x < 8) {
        s = bs[threadIdx.x];
        q = bq[threadIdx.x];
        #pragma unroll
        for (int o = 4; o > 0; o >>= 1) {
            s += __shfl_down_sync(0xffu, s, o);
            q += __shfl_down_sync(0xffu, q, o);
        }
        if (threadIdx.x == 0) {
            atomicAdd(&sum[c], s);
            atomicAdd(&ss[c], q);
        }
    }
}

__global__ void finalize_k(const float* __restrict__ g, const float* __restrict__ be,
                           float invM, const float* __restrict__ sum,
                           const float* __restrict__ ss,
                           float* __restrict__ a, float* __restrict__ b) {
    int c = threadIdx.x;
    if (c < 64) {
        float mean = sum[c] * invM;
        float var  = ss[c] * invM - mean * mean;
        float ai   = g[c] * rsqrtf(var + EPSV);
        a[c] = ai;
        b[c] = be[c] - mean * ai;
    }
}

// -------- BN2 affine + relu -> skip_con; Haar DWT -> g_dwt -------------------
__global__ __launch_bounds__(256) void dwt_k(const float* __restrict__ x2,
                                             const float* __restrict__ a2,
                                             const float* __restrict__ b2,
                                             float* __restrict__ skip,
                                             float* __restrict__ dwt) {
    size_t idx = (size_t)blockIdx.x * 256 + threadIdx.x;  // < 4*64*256*128 = 2^23
    int wp = (int)(idx & 127);
    int h2 = (int)((idx >> 7) & 255);
    int c  = (int)((idx >> 15) & 63);
    int n  = (int)(idx >> 21);

    float a = __ldg(&a2[c]), b = __ldg(&b2[c]);
    size_t ibase = ((size_t)(n * 64 + c)) * 512 * 512 + (size_t)(2 * h2) * 512 + wp * 4;
    float4 r0 = *(const float4*)(x2 + ibase);
    float4 r1 = *(const float4*)(x2 + ibase + 512);
    r0.x = fmaxf(fmaf(r0.x, a, b), 0.f);
    r0.y = fmaxf(fmaf(r0.y, a, b), 0.f);
    r0.z = fmaxf(fmaf(r0.z, a, b), 0.f);
    r0.w = fmaxf(fmaf(r0.w, a, b), 0.f);
    r1.x = fmaxf(fmaf(r1.x, a, b), 0.f);
    r1.y = fmaxf(fmaf(r1.y, a, b), 0.f);
    r1.z = fmaxf(fmaf(r1.z, a, b), 0.f);
    r1.w = fmaxf(fmaf(r1.w, a, b), 0.f);

    *(float4*)(skip + ibase)       = r0;
    *(float4*)(skip + ibase + 512) = r1;

    size_t dbase = ((size_t)(n * 256 + c)) * 256 * 256 + (size_t)h2 * 256 + wp * 2;
    const size_t CH = (size_t)64 * 256 * 256;

    float cA0 = (r0.x + r0.y + r1.x + r1.y) * 0.5f;
    float cH0 = (r0.x + r0.y - r1.x - r1.y) * 0.5f;
    float cV0 = (r0.x - r0.y + r1.x - r1.y) * 0.5f;
    float cD0 = (r0.x - r0.y - r1.x + r1.y) * 0.5f;
    float cA1 = (r0.z + r0.w + r1.z + r1.w) * 0.5f;
    float cH1 = (r0.z + r0.w - r1.z - r1.w) * 0.5f;
    float cV1 = (r0.z - r0.w + r1.z - r1.w) * 0.5f;
    float cD1 = (r0.z - r0.w - r1.z + r1.w) * 0.5f;

    *(float2*)(dwt + dbase)          = make_float2(cA0, cA1);
    *(float2*)(dwt + dbase + CH)     = make_float2(cH0, cH1);
    *(float2*)(dwt + dbase + 2 * CH) = make_float2(cV0, cV1);
    *(float2*)(dwt + dbase + 3 * CH) = make_float2(cD0, cD1);
}

// -------- BN3 affine + relu -> dwt_out --------------------------------------
__global__ __launch_bounds__(256) void bn3relu_k(const float* __restrict__ y3,
                                                 const float* __restrict__ a3,
                                                 const float* __restrict__ b3,
                                                 float* __restrict__ out) {
    size_t idx = (size_t)blockIdx.x * 256 + threadIdx.x;  // < 4*64*256*256 = 2^24
    int c = (int)((idx >> 16) & 63);
    float v = fmaf(y3[idx], __ldg(&a3[c]), __ldg(&b3[c]));
    out[idx] = fmaxf(v, 0.f);
}

// ---------------- host orchestration ----------------------------------------
extern "C" void kernel_launch(void* const* d_in, const int* in_sizes, int n_in,
                              void* d_out, int out_size) {
    const float* inp  = (const float*)d_in[0];
    const float* w1   = (const float*)d_in[1];
    const float* pg1  = (const float*)d_in[3];
    const float* pbe1 = (const float*)d_in[4];
    const float* w2   = (const float*)d_in[5];
    const float* pg2  = (const float*)d_in[7];
    const float* pbe2 = (const float*)d_in[8];
    const float* w3   = (const float*)d_in[9];
    const float* pg3  = (const float*)d_in[11];
    const float* pbe3 = (const float*)d_in[12];

    float* out     = (float*)d_out;
    float* dwt_out = out;                        // 4*64*256*256
    float* skip    = out + 16777216ull;          // 4*64*512*512

    float *x1, *x2, *dwt, *y3, *sum, *ss;
    float *a1, *b1v, *a2, *b2v, *a3, *b3v;
    cudaGetSymbolAddress((void**)&x1,  g_x1);
    cudaGetSymbolAddress((void**)&x2,  g_x2);
    cudaGetSymbolAddress((void**)&dwt, g_dwt);
    cudaGetSymbolAddress((void**)&y3,  g_y3);
    cudaGetSymbolAddress((void**)&sum, g_sum);
    cudaGetSymbolAddress((void**)&ss,  g_ss);
    cudaGetSymbolAddress((void**)&a1,  g_a1);
    cudaGetSymbolAddress((void**)&b1v, g_b1);
    cudaGetSymbolAddress((void**)&a2,  g_a2);
    cudaGetSymbolAddress((void**)&b2v, g_b2);
    cudaGetSymbolAddress((void**)&a3,  g_a3);
    cudaGetSymbolAddress((void**)&b3v, g_b3);

    // conv1 -> x1 (raw, no bias)
    conv1_k<<<4096, 256>>>(inp, w1, x1);

    // BN1 stats -> affine (a1, b1)
    zero_stats_k<<<1, 64>>>(sum, ss);
    stats_k<<<dim3(64, 32), 256>>>(x1, 512 * 512, sum, ss);
    finalize_k<<<1, 64>>>(pg1, pbe1, 1.0f / (4.0f * 512 * 512), sum, ss, a1, b1v);

    // conv2(BN1(x1)) -> x2 (raw)  [tf32 tensor cores]
    convmma_k<64, 512, 512, true><<<dim3(16, 64, 4), 256>>>(x1, w2, a1, b1v, x2);

    // BN2 stats -> affine (a2, b2)
    zero_stats_k<<<1, 64>>>(sum, ss);
    stats_k<<<dim3(64, 32), 256>>>(x2, 512 * 512, sum, ss);
    finalize_k<<<1, 64>>>(pg2, pbe2, 1.0f / (4.0f * 512 * 512), sum, ss, a2, b2v);

    // skip_con = relu(BN2(x2)); dwt = Haar(skip)
    dwt_k<<<32768, 256>>>(x2, a2, b2v, skip, dwt);

    // conv3(dwt) -> y3 (raw)  [tf32 tensor cores]
    convmma_k<256, 256, 256, false><<<dim3(8, 32, 4), 256>>>(dwt, w3, nullptr, nullptr, y3);

    // BN3 stats -> affine (a3, b3)
    zero_stats_k<<<1, 64>>>(sum, ss);
    stats_k<<<dim3(64, 32), 256>>>(y3, 256 * 256, sum, ss);
    finalize_k<<<1, 64>>>(pg3, pbe3, 1.0f / (4.0f * 256 * 256), sum, ss, a3, b3v);

    // dwt_out = relu(BN3(y3))
    bn3relu_k<<<65536, 256>>>(y3, a3, b3v, dwt_out);
}

// round 4
// speedup vs baseline: 3.7013x; 1.1017x over previous
#include <cuda_runtime.h>
#include <math.h>
#include <stdint.h>

// ---------------- scratch buffers (device globals) ---------------------------
__device__ float g_x1[4ull*64*512*512];    // conv1 output (tf32-rounded)
__device__ float g_x2[4ull*64*512*512];    // conv2 raw output
__device__ float g_dwt[4ull*256*256*256];  // DWT of relu(BN2(x2)) (tf32-rounded)
__device__ float g_y3[4ull*64*256*256];    // conv3 raw output
__device__ __align__(16) float g_w2p[8*4608];    // conv2 weights, A-frag layout, *a1, rounded
__device__ __align__(16) float g_w3p[32*4608];   // conv3 weights, A-frag layout, rounded
__device__ float g_T[9*64];                // border bias table for conv2
__device__ float g_sum1[64], g_ss1[64];
__device__ float g_sum2[64], g_ss2[64];
__device__ float g_sum3[64], g_ss3[64];

#define EPSV 1e-5f
#define CI_STRIDE 344    // floats; 344 mod 32 = 24 -> tig offsets {0,24,16,8}: conflict-free

__device__ __forceinline__ float to_tf32(float f) {
    uint32_t r;
    asm("cvt.rna.tf32.f32 %0, %1;" : "=r"(r) : "f"(f));
    return __uint_as_float(r);
}

// ---------------- zero stats -------------------------------------------------
__global__ void zero_k(float* s1, float* q1, float* s2, float* q2,
                       float* s3, float* q3) {
    int t = threadIdx.x;
    if (t < 64) { s1[t]=0.f; q1[t]=0.f; s2[t]=0.f; q2[t]=0.f; s3[t]=0.f; q3[t]=0.f; }
}

// ---------------- conv1: 3->64, 512x512 (stores tf32-rounded) ---------------
__global__ __launch_bounds__(256) void conv1_k(const float* __restrict__ in,
                                               const float* __restrict__ wg,
                                               float* __restrict__ out) {
    __shared__ float s_w[27][64];
    int tid = threadIdx.x;
    for (int idx = tid; idx < 27 * 64; idx += 256) {
        int co = idx & 63;
        int t  = idx >> 6;
        s_w[t][co] = wg[co * 27 + t];
    }
    __syncthreads();

    size_t pid = (size_t)blockIdx.x * 256 + tid;
    int w = (int)(pid & 511);
    int h = (int)((pid >> 9) & 511);
    int n = (int)(pid >> 18);

    const float* inp = in + (size_t)n * 3 * 512 * 512;
    float xv[27];
    int i = 0;
    #pragma unroll
    for (int ci = 0; ci < 3; ci++)
        #pragma unroll
        for (int kh = 0; kh < 3; kh++)
            #pragma unroll
            for (int kw = 0; kw < 3; kw++) {
                int hh = h + kh - 1, ww = w + kw - 1;
                xv[i++] = (hh >= 0 && hh < 512 && ww >= 0 && ww < 512)
                              ? __ldg(&inp[(size_t)ci * 512 * 512 + (size_t)hh * 512 + ww])
                              : 0.f;
            }

    size_t obase = ((size_t)n * 64) * (512 * 512) + (size_t)h * 512 + w;
    for (int co = 0; co < 64; co++) {
        float a = 0.f;
        #pragma unroll
        for (int t = 0; t < 27; t++) a += xv[t] * s_w[t][co];
        out[obase + (size_t)co * 512 * 512] = to_tf32(a);
    }
}

// ---------------- stats over x1 ---------------------------------------------
__global__ void stats_k(const float* __restrict__ x, int HW,
                        float* __restrict__ sum, float* __restrict__ ss) {
    int c = blockIdx.x;
    float s = 0.f, q = 0.f;
    int stride = gridDim.y * blockDim.x;
    int start  = blockIdx.y * blockDim.x + threadIdx.x;
    for (int n = 0; n < 4; n++) {
        const float* p = x + ((size_t)(n * 64 + c)) * HW;
        for (int i = start; i < HW; i += stride) {
            float v = p[i];
            s += v; q += v * v;
        }
    }
    #pragma unroll
    for (int o = 16; o > 0; o >>= 1) {
        s += __shfl_down_sync(0xffffffffu, s, o);
        q += __shfl_down_sync(0xffffffffu, q, o);
    }
    __shared__ float bs[8], bq[8];
    int lane = threadIdx.x & 31, wid = threadIdx.x >> 5;
    if (lane == 0) { bs[wid] = s; bq[wid] = q; }
    __syncthreads();
    if (threadIdx.x < 8) {
        s = bs[threadIdx.x]; q = bq[threadIdx.x];
        #pragma unroll
        for (int o = 4; o > 0; o >>= 1) {
            s += __shfl_down_sync(0xffu, s, o);
            q += __shfl_down_sync(0xffu, q, o);
        }
        if (threadIdx.x == 0) { atomicAdd(&sum[c], s); atomicAdd(&ss[c], q); }
    }
}

// ---------------- prep3: w3 -> A-frag layout, tf32-rounded -------------------
__global__ __launch_bounds__(256) void prep3_k(const float* __restrict__ w3,
                                               float* __restrict__ wp) {
    for (int idx = blockIdx.x * 256 + threadIdx.x; idx < 32 * 4608;
         idx += gridDim.x * 256) {
        int chunk = idx / 4608;
        int rem   = idx - chunk * 4608;
        int tap   = rem >> 9;
        int cog   = (rem >> 7) & 3;
        int l     = (rem >> 2) & 31;
        int j     = rem & 3;
        int co = cog * 16 + (l >> 2) + ((j & 1) ? 8 : 0);
        int ci = chunk * 8 + (l & 3) + ((j & 2) ? 4 : 0);
        wp[idx] = to_tf32(__ldg(&w3[((size_t)co * 256 + ci) * 9 + tap]));
    }
}

// ------- prep2: BN1 finalize folded into w2 (A-frag layout) + border table ---
__global__ __launch_bounds__(256) void prep2_k(const float* __restrict__ w2,
                                               const float* __restrict__ g1,
                                               const float* __restrict__ be1,
                                               const float* __restrict__ sum1,
                                               const float* __restrict__ ss1,
                                               float* __restrict__ wp,
                                               float* __restrict__ Tt) {
    const float invM = 1.0f / (4.0f * 512.0f * 512.0f);
    // transformed weights
    for (int idx = blockIdx.x * 256 + threadIdx.x; idx < 8 * 4608;
         idx += gridDim.x * 256) {
        int chunk = idx / 4608;
        int rem   = idx - chunk * 4608;
        int tap   = rem >> 9;
        int cog   = (rem >> 7) & 3;
        int l     = (rem >> 2) & 31;
        int j     = rem & 3;
        int co = cog * 16 + (l >> 2) + ((j & 1) ? 8 : 0);
        int ci = chunk * 8 + (l & 3) + ((j & 2) ? 4 : 0);
        float mean = __ldg(&sum1[ci]) * invM;
        float var  = __ldg(&ss1[ci]) * invM - mean * mean;
        float a    = __ldg(&g1[ci]) * rsqrtf(var + EPSV);
        wp[idx] = to_tf32(__ldg(&w2[((size_t)co * 64 + ci) * 9 + tap]) * a);
    }
    // border bias table: T[eh*3+ew][co] = sum_ci b1[ci] * sum_{valid taps} w2
    if (blockIdx.x == 0) {
        for (int o = threadIdx.x; o < 9 * 64; o += 256) {
            int e  = o >> 6;
            int co = o & 63;
            int eh = e / 3, ew = e - eh * 3;
            int kh0 = (eh == 0) ? 1 : 0, kh1 = (eh == 2) ? 1 : 2;
            int kw0 = (ew == 0) ? 1 : 0, kw1 = (ew == 2) ? 1 : 2;
            float acc = 0.f;
            for (int ci = 0; ci < 64; ci++) {
                float mean = __ldg(&sum1[ci]) * invM;
                float var  = __ldg(&ss1[ci]) * invM - mean * mean;
                float a    = __ldg(&g1[ci]) * rsqrtf(var + EPSV);
                float b    = __ldg(&be1[ci]) - mean * a;
                float ws = 0.f;
                for (int kh = kh0; kh <= kh1; kh++)
                    for (int kw = kw0; kw <= kw1; kw++)
                        ws += __ldg(&w2[((size_t)co * 64 + ci) * 9 + kh * 3 + kw]);
                acc += b * ws;
            }
            Tt[o] = acc;
        }
    }
}

// ---------------- tf32 mma conv with cp.async double buffering ---------------
// Block: 64co x (8h x 32w), 256 threads = 8 warps.
// Per chunk (8 ci): input tile 8x10x34, weights pre-arranged 4608 floats.
// dyn smem: s_in[2][2752] | s_wf[2][4608] | s_st[128]
template <int C_IN, int H, int W, bool TT>
__global__ __launch_bounds__(256, 2) void convmma_k(const float* __restrict__ in,
                                                    const float* __restrict__ wp,
                                                    const float* __restrict__ Tt,
                                                    float* __restrict__ sum,
                                                    float* __restrict__ ss,
                                                    float* __restrict__ out) {
    extern __shared__ float smem[];
    float* s_in = smem;            // 2 * 2752
    float* s_wf = smem + 5504;     // 2 * 4608
    float* s_st = smem + 14720;    // 128
    uint32_t sb_in = (uint32_t)__cvta_generic_to_shared(s_in);
    uint32_t sb_wf = (uint32_t)__cvta_generic_to_shared(s_wf);

    int n   = blockIdx.z;
    int th0 = blockIdx.y * 8;
    int tw0 = blockIdx.x * 32;
    int tid  = threadIdx.x;
    int warp = tid >> 5;
    int lane = tid & 31;
    int gid  = lane >> 2;
    int tig  = lane & 3;

    if (tid < 128) s_st[tid] = 0.f;

    float c[4][4][4];
    #pragma unroll
    for (int a = 0; a < 4; a++)
        #pragma unroll
        for (int b = 0; b < 4; b++)
            #pragma unroll
            for (int d = 0; d < 4; d++) c[a][b][d] = 0.f;

    const float* in_n = in + (size_t)n * C_IN * H * W;
    const int NCH = C_IN / 8;

    // ---- async stage of one chunk into buffer `buf` ----
    auto issue_chunk = [&](int chunk, int buf) {
        const float* gin = in_n + (size_t)chunk * 8 * H * W;
        #pragma unroll 1
        for (int idx = tid; idx < 2720; idx += 256) {
            int ci  = idx / 340;
            int rem = idx - ci * 340;
            int r   = rem / 34;
            int col = rem - r * 34;
            int gh = th0 + r - 1;
            int gw = tw0 + col - 1;
            bool ok = (gh >= 0 && gh < H && gw >= 0 && gw < W);
            const float* src = ok ? (gin + (size_t)ci * H * W + (size_t)gh * W + gw) : gin;
            uint32_t d = sb_in + (uint32_t)((buf * 2752 + ci * CI_STRIDE + r * 34 + col) * 4);
            int sz = ok ? 4 : 0;
            asm volatile("cp.async.ca.shared.global [%0], [%1], 4, %2;"
                         :: "r"(d), "l"(src), "r"(sz));
        }
        const float* wsrc = wp + (size_t)chunk * 4608;
        #pragma unroll 1
        for (int i = tid; i < 1152; i += 256) {
            uint32_t d = sb_wf + (uint32_t)((buf * 4608 + i * 4) * 4);
            asm volatile("cp.async.cg.shared.global [%0], [%1], 16;"
                         :: "r"(d), "l"(wsrc + i * 4));
        }
        asm volatile("cp.async.commit_group;");
    };

    issue_chunk(0, 0);

    #pragma unroll 1
    for (int ch = 0; ch < NCH; ch++) {
        int buf = ch & 1;
        if (ch + 1 < NCH) {
            issue_chunk(ch + 1, buf ^ 1);
            asm volatile("cp.async.wait_group 1;");
        } else {
            asm volatile("cp.async.wait_group 0;");
        }
        __syncthreads();

        const float4* wf4 = (const float4*)(s_wf + buf * 4608);
        const float*  sib = s_in + buf * 2752;

        #pragma unroll
        for (int kh = 0; kh < 3; kh++) {
            #pragma unroll
            for (int kw = 0; kw < 3; kw++) {
                int tap = kh * 3 + kw;
                uint32_t A[4][4];
                #pragma unroll
                for (int cog = 0; cog < 4; cog++) {
                    float4 a4 = wf4[(tap * 4 + cog) * 32 + lane];
                    A[cog][0] = __float_as_uint(a4.x);
                    A[cog][1] = __float_as_uint(a4.y);
                    A[cog][2] = __float_as_uint(a4.z);
                    A[cog][3] = __float_as_uint(a4.w);
                }
                int rbase = (warp + kh) * 34;
                #pragma unroll
                for (int pf = 0; pf < 4; pf++) {
                    int col = pf * 8 + gid + kw;
                    uint32_t b0 = __float_as_uint(sib[tig * CI_STRIDE + rbase + col]);
                    uint32_t b1 = __float_as_uint(sib[(tig + 4) * CI_STRIDE + rbase + col]);
                    #pragma unroll
                    for (int cog = 0; cog < 4; cog++) {
                        asm volatile(
                            "mma.sync.aligned.m16n8k8.row.col.f32.tf32.tf32.f32 "
                            "{%0,%1,%2,%3}, {%4,%5,%6,%7}, {%8,%9}, {%0,%1,%2,%3};\n"
                            : "+f"(c[cog][pf][0]), "+f"(c[cog][pf][1]),
                              "+f"(c[cog][pf][2]), "+f"(c[cog][pf][3])
                            : "r"(A[cog][0]), "r"(A[cog][1]), "r"(A[cog][2]), "r"(A[cog][3]),
                              "r"(b0), "r"(b1));
                    }
                }
            }
        }
        __syncthreads();
    }

    // ---- epilogue: optional border-bias, stores, fused stats ----
    int h = th0 + warp;
    float* op = out + ((size_t)n * 64) * H * W + (size_t)h * W + tw0;
    int eh = (h == 0) ? 0 : ((h == H - 1) ? 2 : 1);
    float csum[8], csq[8];
    #pragma unroll
    for (int q = 0; q < 8; q++) { csum[q] = 0.f; csq[q] = 0.f; }

    #pragma unroll
    for (int cog = 0; cog < 4; cog++) {
        int coA = cog * 16 + gid;
        int coB = coA + 8;
        #pragma unroll
        for (int pf = 0; pf < 4; pf++) {
            int w0 = tw0 + pf * 8 + tig * 2;
            float v0 = c[cog][pf][0], v1 = c[cog][pf][1];
            float v2 = c[cog][pf][2], v3 = c[cog][pf][3];
            if (TT) {
                int ew0 = (w0 == 0) ? 0 : ((w0 == W - 1) ? 2 : 1);
                int ew1 = ((w0 + 1) == W - 1) ? 2 : 1;  // w0+1 >= 1 always
                v0 += __ldg(&Tt[(eh * 3 + ew0) * 64 + coA]);
                v1 += __ldg(&Tt[(eh * 3 + ew1) * 64 + coA]);
                v2 += __ldg(&Tt[(eh * 3 + ew0) * 64 + coB]);
                v3 += __ldg(&Tt[(eh * 3 + ew1) * 64 + coB]);
            }
            *(float2*)(op + (size_t)coA * H * W + pf * 8 + tig * 2) = make_float2(v0, v1);
            *(float2*)(op + (size_t)coB * H * W + pf * 8 + tig * 2) = make_float2(v2, v3);
            csum[cog * 2]     += v0 + v1;
            csq[cog * 2]      += v0 * v0 + v1 * v1;
            csum[cog * 2 + 1] += v2 + v3;
            csq[cog * 2 + 1]  += v2 * v2 + v3 * v3;
        }
    }
    #pragma unroll
    for (int q = 0; q < 8; q++) {
        int co = (q >> 1) * 16 + gid + ((q & 1) ? 8 : 0);
        atomicAdd(&s_st[co], csum[q]);
        atomicAdd(&s_st[64 + co], csq[q]);
    }
    __syncthreads();
    if (tid < 64) {
        atomicAdd(&sum[tid], s_st[tid]);
        atomicAdd(&ss[tid], s_st[64 + tid]);
    }
}

// -------- BN2 (inline finalize) + relu -> skip; Haar DWT (rounded) -> g_dwt --
__global__ __launch_bounds__(256) void dwt_k(const float* __restrict__ x2,
                                             const float* __restrict__ g2,
                                             const float* __restrict__ be2,
                                             const float* __restrict__ sum2,
                                             const float* __restrict__ ss2,
                                             float* __restrict__ skip,
                                             float* __restrict__ dwt) {
    size_t idx = (size_t)blockIdx.x * 256 + threadIdx.x;
    int wp = (int)(idx & 127);
    int h2 = (int)((idx >> 7) & 255);
    int c  = (int)((idx >> 15) & 63);
    int n  = (int)(idx >> 21);

    const float invM = 1.0f / (4.0f * 512.0f * 512.0f);
    float mean = __ldg(&sum2[c]) * invM;
    float var  = __ldg(&ss2[c]) * invM - mean * mean;
    float a    = __ldg(&g2[c]) * rsqrtf(var + EPSV);
    float b    = __ldg(&be2[c]) - mean * a;

    size_t ibase = ((size_t)(n * 64 + c)) * 512 * 512 + (size_t)(2 * h2) * 512 + wp * 4;
    float4 r0 = *(const float4*)(x2 + ibase);
    float4 r1 = *(const float4*)(x2 + ibase + 512);
    r0.x = fmaxf(fmaf(r0.x, a, b), 0.f);
    r0.y = fmaxf(fmaf(r0.y, a, b), 0.f);
    r0.z = fmaxf(fmaf(r0.z, a, b), 0.f);
    r0.w = fmaxf(fmaf(r0.w, a, b), 0.f);
    r1.x = fmaxf(fmaf(r1.x, a, b), 0.f);
    r1.y = fmaxf(fmaf(r1.y, a, b), 0.f);
    r1.z = fmaxf(fmaf(r1.z, a, b), 0.f);
    r1.w = fmaxf(fmaf(r1.w, a, b), 0.f);

    *(float4*)(skip + ibase)       = r0;
    *(float4*)(skip + ibase + 512) = r1;

    size_t dbase = ((size_t)(n * 256 + c)) * 256 * 256 + (size_t)h2 * 256 + wp * 2;
    const size_t CH = (size_t)64 * 256 * 256;

    float cA0 = (r0.x + r0.y + r1.x + r1.y) * 0.5f;
    float cH0 = (r0.x + r0.y - r1.x - r1.y) * 0.5f;
    float cV0 = (r0.x - r0.y + r1.x - r1.y) * 0.5f;
    float cD0 = (r0.x - r0.y - r1.x + r1.y) * 0.5f;
    float cA1 = (r0.z + r0.w + r1.z + r1.w) * 0.5f;
    float cH1 = (r0.z + r0.w - r1.z - r1.w) * 0.5f;
    float cV1 = (r0.z - r0.w + r1.z - r1.w) * 0.5f;
    float cD1 = (r0.z - r0.w - r1.z + r1.w) * 0.5f;

    *(float2*)(dwt + dbase)          = make_float2(to_tf32(cA0), to_tf32(cA1));
    *(float2*)(dwt + dbase + CH)     = make_float2(to_tf32(cH0), to_tf32(cH1));
    *(float2*)(dwt + dbase + 2 * CH) = make_float2(to_tf32(cV0), to_tf32(cV1));
    *(float2*)(dwt + dbase + 3 * CH) = make_float2(to_tf32(cD0), to_tf32(cD1));
}

// -------- BN3 (inline finalize) + relu -> dwt_out ----------------------------
__global__ __launch_bounds__(256) void bn3relu_k(const float* __restrict__ y3,
                                                 const float* __restrict__ g3,
                                                 const float* __restrict__ be3,
                                                 const float* __restrict__ sum3,
                                                 const float* __restrict__ ss3,
                                                 float* __restrict__ out) {
    size_t idx = (size_t)blockIdx.x * 256 + threadIdx.x;
    int c = (int)((idx >> 16) & 63);
    const float invM = 1.0f / (4.0f * 256.0f * 256.0f);
    float mean = __ldg(&sum3[c]) * invM;
    float var  = __ldg(&ss3[c]) * invM - mean * mean;
    float a    = __ldg(&g3[c]) * rsqrtf(var + EPSV);
    float b    = __ldg(&be3[c]) - mean * a;
    out[idx] = fmaxf(fmaf(y3[idx], a, b), 0.f);
}

// ---------------- host orchestration ----------------------------------------
extern "C" void kernel_launch(void* const* d_in, const int* in_sizes, int n_in,
                              void* d_out, int out_size) {
    const float* inp  = (const float*)d_in[0];
    const float* w1   = (const float*)d_in[1];
    const float* pg1  = (const float*)d_in[3];
    const float* pbe1 = (const float*)d_in[4];
    const float* w2   = (const float*)d_in[5];
    const float* pg2  = (const float*)d_in[7];
    const float* pbe2 = (const float*)d_in[8];
    const float* w3   = (const float*)d_in[9];
    const float* pg3  = (const float*)d_in[11];
    const float* pbe3 = (const float*)d_in[12];

    float* out     = (float*)d_out;
    float* dwt_out = out;
    float* skip    = out + 16777216ull;

    float *x1, *x2, *dwt, *y3, *w2p, *w3p, *Tt;
    float *s1, *q1, *s2, *q2, *s3, *q3;
    cudaGetSymbolAddress((void**)&x1,  g_x1);
    cudaGetSymbolAddress((void**)&x2,  g_x2);
    cudaGetSymbolAddress((void**)&dwt, g_dwt);
    cudaGetSymbolAddress((void**)&y3,  g_y3);
    cudaGetSymbolAddress((void**)&w2p, g_w2p);
    cudaGetSymbolAddress((void**)&w3p, g_w3p);
    cudaGetSymbolAddress((void**)&Tt,  g_T);
    cudaGetSymbolAddress((void**)&s1,  g_sum1);
    cudaGetSymbolAddress((void**)&q1,  g_ss1);
    cudaGetSymbolAddress((void**)&s2,  g_sum2);
    cudaGetSymbolAddress((void**)&q2,  g_ss2);
    cudaGetSymbolAddress((void**)&s3,  g_sum3);
    cudaGetSymbolAddress((void**)&q3,  g_ss3);

    const int SMEM = (5504 + 9216 + 128) * 4;  // 59392 B
    cudaFuncSetAttribute(convmma_k<64, 512, 512, true>,
                         cudaFuncAttributeMaxDynamicSharedMemorySize, SMEM);
    cudaFuncSetAttribute(convmma_k<256, 256, 256, false>,
                         cudaFuncAttributeMaxDynamicSharedMemorySize, SMEM);

    // 1
    zero_k<<<1, 64>>>(s1, q1, s2, q2, s3, q3);
    // 2
    prep3_k<<<64, 256>>>(w3, w3p);
    // 3
    conv1_k<<<4096, 256>>>(inp, w1, x1);
    // 4
    stats_k<<<dim3(64, 32), 256>>>(x1, 512 * 512, s1, q1);
    // 5
    prep2_k<<<64, 256>>>(w2, pg1, pbe1, s1, q1, w2p, Tt);
    // 6  <- profiled by ncu (-s 5 -c 1)
    convmma_k<64, 512, 512, true><<<dim3(16, 64, 4), 256, SMEM>>>(
        x1, w2p, Tt, s2, q2, x2);
    // 7
    dwt_k<<<32768, 256>>>(x2, pg2, pbe2, s2, q2, skip, dwt);
    // 8
    convmma_k<256, 256, 256, false><<<dim3(8, 32, 4), 256, SMEM>>>(
        dwt, w3p, nullptr, s3, q3, y3);
    // 9
    bn3relu_k<<<65536, 256>>>(y3, pg3, pbe3, s3, q3, dwt_out);
}

// round 5
// speedup vs baseline: 4.2427x; 1.1463x over previous
#include <cuda_runtime.h>
#include <math.h>
#include <stdint.h>

// ---------------- scratch buffers (device globals) ---------------------------
__device__ float g_x1[4ull*64*512*512];    // conv1 output (tf32-rounded)
__device__ float g_x2[4ull*64*512*512];    // conv2 raw output
__device__ float g_dwt[4ull*256*256*256];  // DWT of relu(BN2(x2)) (tf32-rounded)
__device__ float g_y3[4ull*64*256*256];    // conv3 raw output
__device__ __align__(16) float g_w2p[8*4608];    // conv2 weights, A-frag, *a1, rounded
__device__ __align__(16) float g_w3p[32*4608];   // conv3 weights, A-frag, rounded
__device__ float g_T[9*64];                // border bias table for conv2
__device__ float g_sum1[64], g_ss1[64];
__device__ float g_sum2[64], g_ss2[64];
__device__ float g_sum3[64], g_ss3[64];

#define EPSV 1e-5f
#define CI_STRIDE 344    // floats; 344 mod 32 = 24 -> tig offsets {0,24,16,8}: conflict-free

__device__ __forceinline__ float to_tf32(float f) {
    uint32_t r;
    asm("cvt.rna.tf32.f32 %0, %1;" : "=r"(r) : "f"(f));
    return __uint_as_float(r);
}

// ------ conv1: 3->64, 512x512 (tf32-rounded out) + fused stats-zero ----------
__global__ __launch_bounds__(256) void conv1_k(const float* __restrict__ in,
                                               const float* __restrict__ wg,
                                               float* __restrict__ out,
                                               float* __restrict__ z0,
                                               float* __restrict__ z1,
                                               float* __restrict__ z2,
                                               float* __restrict__ z3,
                                               float* __restrict__ z4,
                                               float* __restrict__ z5) {
    __shared__ __align__(16) float s_w[27][64];
    int tid = threadIdx.x;
    if (blockIdx.x == 0 && tid < 64) {
        z0[tid]=0.f; z1[tid]=0.f; z2[tid]=0.f; z3[tid]=0.f; z4[tid]=0.f; z5[tid]=0.f;
    }
    for (int idx = tid; idx < 27 * 64; idx += 256) {
        int co = idx & 63;
        int t  = idx >> 6;
        s_w[t][co] = wg[co * 27 + t];
    }
    __syncthreads();

    size_t pid = (size_t)blockIdx.x * 256 + tid;
    int w = (int)(pid & 511);
    int h = (int)((pid >> 9) & 511);
    int n = (int)(pid >> 18);

    const float* inp = in + (size_t)n * 3 * 512 * 512;
    float xv[27];
    int i = 0;
    #pragma unroll
    for (int ci = 0; ci < 3; ci++)
        #pragma unroll
        for (int kh = 0; kh < 3; kh++)
            #pragma unroll
            for (int kw = 0; kw < 3; kw++) {
                int hh = h + kh - 1, ww = w + kw - 1;
                xv[i++] = (hh >= 0 && hh < 512 && ww >= 0 && ww < 512)
                              ? __ldg(&inp[(size_t)ci * 512 * 512 + (size_t)hh * 512 + ww])
                              : 0.f;
            }

    size_t obase = ((size_t)n * 64) * (512 * 512) + (size_t)h * 512 + w;
    #pragma unroll 1
    for (int cog = 0; cog < 16; cog++) {
        float a0 = 0.f, a1 = 0.f, a2 = 0.f, a3 = 0.f;
        #pragma unroll
        for (int t = 0; t < 27; t++) {
            float4 w4 = *(const float4*)&s_w[t][cog * 4];
            a0 += xv[t] * w4.x;
            a1 += xv[t] * w4.y;
            a2 += xv[t] * w4.z;
            a3 += xv[t] * w4.w;
        }
        size_t ob = obase + (size_t)(cog * 4) * 512 * 512;
        out[ob]                    = to_tf32(a0);
        out[ob + 1ull*512*512]     = to_tf32(a1);
        out[ob + 2ull*512*512]     = to_tf32(a2);
        out[ob + 3ull*512*512]     = to_tf32(a3);
    }
}

// ---------------- stats over x1 (float4) -------------------------------------
__global__ void stats_k(const float* __restrict__ x, int HW,
                        float* __restrict__ sum, float* __restrict__ ss) {
    int c = blockIdx.x;
    float s = 0.f, q = 0.f;
    int stride = gridDim.y * blockDim.x;
    int start  = blockIdx.y * blockDim.x + threadIdx.x;
    int HW4 = HW >> 2;
    for (int n = 0; n < 4; n++) {
        const float4* p = (const float4*)(x + ((size_t)(n * 64 + c)) * HW);
        for (int i = start; i < HW4; i += stride) {
            float4 v = p[i];
            s += v.x + v.y + v.z + v.w;
            q += v.x * v.x + v.y * v.y + v.z * v.z + v.w * v.w;
        }
    }
    #pragma unroll
    for (int o = 16; o > 0; o >>= 1) {
        s += __shfl_down_sync(0xffffffffu, s, o);
        q += __shfl_down_sync(0xffffffffu, q, o);
    }
    __shared__ float bs[8], bq[8];
    int lane = threadIdx.x & 31, wid = threadIdx.x >> 5;
    if (lane == 0) { bs[wid] = s; bq[wid] = q; }
    __syncthreads();
    if (threadIdx.x < 8) {
        s = bs[threadIdx.x]; q = bq[threadIdx.x];
        #pragma unroll
        for (int o = 4; o > 0; o >>= 1) {
            s += __shfl_down_sync(0xffu, s, o);
            q += __shfl_down_sync(0xffu, q, o);
        }
        if (threadIdx.x == 0) { atomicAdd(&sum[c], s); atomicAdd(&ss[c], q); }
    }
}

// ---------------- prep3: w3 -> A-frag layout, tf32-rounded -------------------
__global__ __launch_bounds__(256) void prep3_k(const float* __restrict__ w3,
                                               float* __restrict__ wp) {
    for (int idx = blockIdx.x * 256 + threadIdx.x; idx < 32 * 4608;
         idx += gridDim.x * 256) {
        int chunk = idx / 4608;
        int rem   = idx - chunk * 4608;
        int tap   = rem >> 9;
        int cog   = (rem >> 7) & 3;
        int l     = (rem >> 2) & 31;
        int j     = rem & 3;
        int co = cog * 16 + (l >> 2) + ((j & 1) ? 8 : 0);
        int ci = chunk * 8 + (l & 3) + ((j & 2) ? 4 : 0);
        wp[idx] = to_tf32(__ldg(&w3[((size_t)co * 256 + ci) * 9 + tap]));
    }
}

// ------- prep2: BN1 finalize folded into w2 (A-frag layout) + border table ---
__global__ __launch_bounds__(256) void prep2_k(const float* __restrict__ w2,
                                               const float* __restrict__ g1,
                                               const float* __restrict__ be1,
                                               const float* __restrict__ sum1,
                                               const float* __restrict__ ss1,
                                               float* __restrict__ wp,
                                               float* __restrict__ Tt) {
    const float invM = 1.0f / (4.0f * 512.0f * 512.0f);
    for (int idx = blockIdx.x * 256 + threadIdx.x; idx < 8 * 4608;
         idx += gridDim.x * 256) {
        int chunk = idx / 4608;
        int rem   = idx - chunk * 4608;
        int tap   = rem >> 9;
        int cog   = (rem >> 7) & 3;
        int l     = (rem >> 2) & 31;
        int j     = rem & 3;
        int co = cog * 16 + (l >> 2) + ((j & 1) ? 8 : 0);
        int ci = chunk * 8 + (l & 3) + ((j & 2) ? 4 : 0);
        float mean = __ldg(&sum1[ci]) * invM;
        float var  = __ldg(&ss1[ci]) * invM - mean * mean;
        float a    = __ldg(&g1[ci]) * rsqrtf(var + EPSV);
        wp[idx] = to_tf32(__ldg(&w2[((size_t)co * 64 + ci) * 9 + tap]) * a);
    }
    if (blockIdx.x == 0) {
        for (int o = threadIdx.x; o < 9 * 64; o += 256) {
            int e  = o >> 6;
            int co = o & 63;
            int eh = e / 3, ew = e - eh * 3;
            int kh0 = (eh == 0) ? 1 : 0, kh1 = (eh == 2) ? 1 : 2;
            int kw0 = (ew == 0) ? 1 : 0, kw1 = (ew == 2) ? 1 : 2;
            float acc = 0.f;
            for (int ci = 0; ci < 64; ci++) {
                float mean = __ldg(&sum1[ci]) * invM;
                float var  = __ldg(&ss1[ci]) * invM - mean * mean;
                float a    = __ldg(&g1[ci]) * rsqrtf(var + EPSV);
                float b    = __ldg(&be1[ci]) - mean * a;
                float ws = 0.f;
                for (int kh = kh0; kh <= kh1; kh++)
                    for (int kw = kw0; kw <= kw1; kw++)
                        ws += __ldg(&w2[((size_t)co * 64 + ci) * 9 + kh * 3 + kw]);
                acc += b * ws;
            }
            Tt[o] = acc;
        }
    }
}

// ------- tf32 mma conv, 3-stage cp.async pipeline, 1 sync per chunk ----------
// dyn smem: s_in[3][2752] | s_wf[3][4608] | s_st[128]  = 88832 B
#define IN_SZ 2752
#define WF_SZ 4608

template <int C_IN, int H, int W, bool TT>
__global__ __launch_bounds__(256, 2) void convmma_k(const float* __restrict__ in,
                                                    const float* __restrict__ wp,
                                                    const float* __restrict__ Tt,
                                                    float* __restrict__ sum,
                                                    float* __restrict__ ss,
                                                    float* __restrict__ out) {
    extern __shared__ float smem[];
    float* s_in = smem;                        // 3 * 2752
    float* s_wf = smem + 3 * IN_SZ;            // 3 * 4608
    float* s_st = smem + 3 * IN_SZ + 3 * WF_SZ;// 128
    uint32_t sb_in = (uint32_t)__cvta_generic_to_shared(s_in);
    uint32_t sb_wf = (uint32_t)__cvta_generic_to_shared(s_wf);

    int n   = blockIdx.z;
    int th0 = blockIdx.y * 8;
    int tw0 = blockIdx.x * 32;
    int tid  = threadIdx.x;
    int warp = tid >> 5;
    int lane = tid & 31;
    int gid  = lane >> 2;
    int tig  = lane & 3;

    if (tid < 128) s_st[tid] = 0.f;

    float c[4][4][4];
    #pragma unroll
    for (int a = 0; a < 4; a++)
        #pragma unroll
        for (int b = 0; b < 4; b++)
            #pragma unroll
            for (int d = 0; d < 4; d++) c[a][b][d] = 0.f;

    const float* in_n = in + (size_t)n * C_IN * H * W;
    const int NCH = C_IN / 8;

    auto issue_chunk = [&](int chunk, int buf) {
        const float* gin = in_n + (size_t)chunk * 8 * H * W;
        #pragma unroll 1
        for (int idx = tid; idx < 2720; idx += 256) {
            int ci  = idx / 340;
            int rem = idx - ci * 340;
            int r   = rem / 34;
            int col = rem - r * 34;
            int gh = th0 + r - 1;
            int gw = tw0 + col - 1;
            bool ok = (gh >= 0 && gh < H && gw >= 0 && gw < W);
            const float* src = ok ? (gin + (size_t)ci * H * W + (size_t)gh * W + gw) : gin;
            uint32_t d = sb_in + (uint32_t)((buf * IN_SZ + ci * CI_STRIDE + r * 34 + col) * 4);
            int sz = ok ? 4 : 0;
            asm volatile("cp.async.ca.shared.global [%0], [%1], 4, %2;"
                         :: "r"(d), "l"(src), "r"(sz));
        }
        const float* wsrc = wp + (size_t)chunk * WF_SZ;
        #pragma unroll 1
        for (int i = tid; i < 1152; i += 256) {
            uint32_t d = sb_wf + (uint32_t)((buf * WF_SZ + i * 4) * 4);
            asm volatile("cp.async.cg.shared.global [%0], [%1], 16;"
                         :: "r"(d), "l"(wsrc + i * 4));
        }
        asm volatile("cp.async.commit_group;");
    };

    issue_chunk(0, 0);
    if (NCH > 1) issue_chunk(1, 1);

    int buf = 0;
    #pragma unroll 1
    for (int ch = 0; ch < NCH; ch++) {
        if (ch + 1 < NCH) {
            asm volatile("cp.async.wait_group 1;");
        } else {
            asm volatile("cp.async.wait_group 0;");
        }
        __syncthreads();
        if (ch + 2 < NCH) {
            int nbuf = buf + 2; if (nbuf >= 3) nbuf -= 3;
            issue_chunk(ch + 2, nbuf);
        }

        const float4* wf4 = (const float4*)(s_wf + buf * WF_SZ);
        const float*  sib = s_in + buf * IN_SZ;

        #pragma unroll
        for (int kh = 0; kh < 3; kh++) {
            #pragma unroll
            for (int kw = 0; kw < 3; kw++) {
                int tap = kh * 3 + kw;
                uint32_t A[4][4];
                #pragma unroll
                for (int cog = 0; cog < 4; cog++) {
                    float4 a4 = wf4[(tap * 4 + cog) * 32 + lane];
                    A[cog][0] = __float_as_uint(a4.x);
                    A[cog][1] = __float_as_uint(a4.y);
                    A[cog][2] = __float_as_uint(a4.z);
                    A[cog][3] = __float_as_uint(a4.w);
                }
                int rbase = (warp + kh) * 34;
                #pragma unroll
                for (int pf = 0; pf < 4; pf++) {
                    int col = pf * 8 + gid + kw;
                    uint32_t b0 = __float_as_uint(sib[tig * CI_STRIDE + rbase + col]);
                    uint32_t b1 = __float_as_uint(sib[(tig + 4) * CI_STRIDE + rbase + col]);
                    #pragma unroll
                    for (int cog = 0; cog < 4; cog++) {
                        asm volatile(
                            "mma.sync.aligned.m16n8k8.row.col.f32.tf32.tf32.f32 "
                            "{%0,%1,%2,%3}, {%4,%5,%6,%7}, {%8,%9}, {%0,%1,%2,%3};\n"
                            : "+f"(c[cog][pf][0]), "+f"(c[cog][pf][1]),
                              "+f"(c[cog][pf][2]), "+f"(c[cog][pf][3])
                            : "r"(A[cog][0]), "r"(A[cog][1]), "r"(A[cog][2]), "r"(A[cog][3]),
                              "r"(b0), "r"(b1));
                    }
                }
            }
        }
        buf++; if (buf >= 3) buf = 0;
    }

    // ---- epilogue: optional border-bias, stores, fused stats ----
    int h = th0 + warp;
    float* op = out + ((size_t)n * 64) * H * W + (size_t)h * W + tw0;
    int eh = (h == 0) ? 0 : ((h == H - 1) ? 2 : 1);
    float csum[8], csq[8];
    #pragma unroll
    for (int q = 0; q < 8; q++) { csum[q] = 0.f; csq[q] = 0.f; }

    #pragma unroll
    for (int cog = 0; cog < 4; cog++) {
        int coA = cog * 16 + gid;
        int coB = coA + 8;
        #pragma unroll
        for (int pf = 0; pf < 4; pf++) {
            int w0 = tw0 + pf * 8 + tig * 2;
            float v0 = c[cog][pf][0], v1 = c[cog][pf][1];
            float v2 = c[cog][pf][2], v3 = c[cog][pf][3];
            if (TT) {
                int ew0 = (w0 == 0) ? 0 : ((w0 == W - 1) ? 2 : 1);
                int ew1 = ((w0 + 1) == W - 1) ? 2 : 1;
                v0 += __ldg(&Tt[(eh * 3 + ew0) * 64 + coA]);
                v1 += __ldg(&Tt[(eh * 3 + ew1) * 64 + coA]);
                v2 += __ldg(&Tt[(eh * 3 + ew0) * 64 + coB]);
                v3 += __ldg(&Tt[(eh * 3 + ew1) * 64 + coB]);
            }
            *(float2*)(op + (size_t)coA * H * W + pf * 8 + tig * 2) = make_float2(v0, v1);
            *(float2*)(op + (size_t)coB * H * W + pf * 8 + tig * 2) = make_float2(v2, v3);
            csum[cog * 2]     += v0 + v1;
            csq[cog * 2]      += v0 * v0 + v1 * v1;
            csum[cog * 2 + 1] += v2 + v3;
            csq[cog * 2 + 1]  += v2 * v2 + v3 * v3;
        }
    }
    #pragma unroll
    for (int q = 0; q < 8; q++) {
        int co = (q >> 1) * 16 + gid + ((q & 1) ? 8 : 0);
        atomicAdd(&s_st[co], csum[q]);
        atomicAdd(&s_st[64 + co], csq[q]);
    }
    __syncthreads();
    if (tid < 64) {
        atomicAdd(&sum[tid], s_st[tid]);
        atomicAdd(&ss[tid], s_st[64 + tid]);
    }
}

// -------- BN2 (inline finalize) + relu -> skip; Haar DWT (rounded) -> g_dwt --
__global__ __launch_bounds__(256) void dwt_k(const float* __restrict__ x2,
                                             const float* __restrict__ g2,
                                             const float* __restrict__ be2,
                                             const float* __restrict__ sum2,
                                             const float* __restrict__ ss2,
                                             float* __restrict__ skip,
                                             float* __restrict__ dwt) {
    size_t idx = (size_t)blockIdx.x * 256 + threadIdx.x;
    int wp = (int)(idx & 127);
    int h2 = (int)((idx >> 7) & 255);
    int c  = (int)((idx >> 15) & 63);
    int n  = (int)(idx >> 21);

    const float invM = 1.0f / (4.0f * 512.0f * 512.0f);
    float mean = __ldg(&sum2[c]) * invM;
    float var  = __ldg(&ss2[c]) * invM - mean * mean;
    float a    = __ldg(&g2[c]) * rsqrtf(var + EPSV);
    float b    = __ldg(&be2[c]) - mean * a;

    size_t ibase = ((size_t)(n * 64 + c)) * 512 * 512 + (size_t)(2 * h2) * 512 + wp * 4;
    float4 r0 = *(const float4*)(x2 + ibase);
    float4 r1 = *(const float4*)(x2 + ibase + 512);
    r0.x = fmaxf(fmaf(r0.x, a, b), 0.f);
    r0.y = fmaxf(fmaf(r0.y, a, b), 0.f);
    r0.z = fmaxf(fmaf(r0.z, a, b), 0.f);
    r0.w = fmaxf(fmaf(r0.w, a, b), 0.f);
    r1.x = fmaxf(fmaf(r1.x, a, b), 0.f);
    r1.y = fmaxf(fmaf(r1.y, a, b), 0.f);
    r1.z = fmaxf(fmaf(r1.z, a, b), 0.f);
    r1.w = fmaxf(fmaf(r1.w, a, b), 0.f);

    *(float4*)(skip + ibase)       = r0;
    *(float4*)(skip + ibase + 512) = r1;

    size_t dbase = ((size_t)(n * 256 + c)) * 256 * 256 + (size_t)h2 * 256 + wp * 2;
    const size_t CH = (size_t)64 * 256 * 256;

    float cA0 = (r0.x + r0.y + r1.x + r1.y) * 0.5f;
    float cH0 = (r0.x + r0.y - r1.x - r1.y) * 0.5f;
    float cV0 = (r0.x - r0.y + r1.x - r1.y) * 0.5f;
    float cD0 = (r0.x - r0.y - r1.x + r1.y) * 0.5f;
    float cA1 = (r0.z + r0.w + r1.z + r1.w) * 0.5f;
    float cH1 = (r0.z + r0.w - r1.z - r1.w) * 0.5f;
    float cV1 = (r0.z - r0.w + r1.z - r1.w) * 0.5f;
    float cD1 = (r0.z - r0.w - r1.z + r1.w) * 0.5f;

    *(float2*)(dwt + dbase)          = make_float2(to_tf32(cA0), to_tf32(cA1));
    *(float2*)(dwt + dbase + CH)     = make_float2(to_tf32(cH0), to_tf32(cH1));
    *(float2*)(dwt + dbase + 2 * CH) = make_float2(to_tf32(cV0), to_tf32(cV1));
    *(float2*)(dwt + dbase + 3 * CH) = make_float2(to_tf32(cD0), to_tf32(cD1));
}

// -------- BN3 (inline finalize) + relu -> dwt_out ----------------------------
__global__ __launch_bounds__(256) void bn3relu_k(const float* __restrict__ y3,
                                                 const float* __restrict__ g3,
                                                 const float* __restrict__ be3,
                                                 const float* __restrict__ sum3,
                                                 const float* __restrict__ ss3,
                                                 float* __restrict__ out) {
    size_t idx = (size_t)blockIdx.x * 256 + threadIdx.x;
    int c = (int)((idx >> 16) & 63);
    const float invM = 1.0f / (4.0f * 256.0f * 256.0f);
    float mean = __ldg(&sum3[c]) * invM;
    float var  = __ldg(&ss3[c]) * invM - mean * mean;
    float a    = __ldg(&g3[c]) * rsqrtf(var + EPSV);
    float b    = __ldg(&be3[c]) - mean * a;
    out[idx] = fmaxf(fmaf(y3[idx], a, b), 0.f);
}

// ---------------- host orchestration ----------------------------------------
extern "C" void kernel_launch(void* const* d_in, const int* in_sizes, int n_in,
                              void* d_out, int out_size) {
    const float* inp  = (const float*)d_in[0];
    const float* w1   = (const float*)d_in[1];
    const float* pg1  = (const float*)d_in[3];
    const float* pbe1 = (const float*)d_in[4];
    const float* w2   = (const float*)d_in[5];
    const float* pg2  = (const float*)d_in[7];
    const float* pbe2 = (const float*)d_in[8];
    const float* w3   = (const float*)d_in[9];
    const float* pg3  = (const float*)d_in[11];
    const float* pbe3 = (const float*)d_in[12];

    float* out     = (float*)d_out;
    float* dwt_out = out;
    float* skip    = out + 16777216ull;

    float *x1, *x2, *dwt, *y3, *w2p, *w3p, *Tt;
    float *s1, *q1, *s2, *q2, *s3, *q3;
    cudaGetSymbolAddress((void**)&x1,  g_x1);
    cudaGetSymbolAddress((void**)&x2,  g_x2);
    cudaGetSymbolAddress((void**)&dwt, g_dwt);
    cudaGetSymbolAddress((void**)&y3,  g_y3);
    cudaGetSymbolAddress((void**)&w2p, g_w2p);
    cudaGetSymbolAddress((void**)&w3p, g_w3p);
    cudaGetSymbolAddress((void**)&Tt,  g_T);
    cudaGetSymbolAddress((void**)&s1,  g_sum1);
    cudaGetSymbolAddress((void**)&q1,  g_ss1);
    cudaGetSymbolAddress((void**)&s2,  g_sum2);
    cudaGetSymbolAddress((void**)&q2,  g_ss2);
    cudaGetSymbolAddress((void**)&s3,  g_sum3);
    cudaGetSymbolAddress((void**)&q3,  g_ss3);

    const int SMEM = (3 * IN_SZ + 3 * WF_SZ + 128) * 4;  // 88832 B
    cudaFuncSetAttribute(convmma_k<64, 512, 512, true>,
                         cudaFuncAttributeMaxDynamicSharedMemorySize, SMEM);
    cudaFuncSetAttribute(convmma_k<256, 256, 256, false>,
                         cudaFuncAttributeMaxDynamicSharedMemorySize, SMEM);

    // 1: conv1 (+ zero all stats)
    conv1_k<<<4096, 256>>>(inp, w1, x1, s1, q1, s2, q2, s3, q3);
    // 2: BN1 stats
    stats_k<<<dim3(64, 32), 256>>>(x1, 512 * 512, s1, q1);
    // 3: fold BN1 into conv2 weights + border table
    prep2_k<<<64, 256>>>(w2, pg1, pbe1, s1, q1, w2p, Tt);
    // 4: conv2  <- ncu profiles launch #4
    convmma_k<64, 512, 512, true><<<dim3(16, 64, 4), 256, SMEM>>>(
        x1, w2p, Tt, s2, q2, x2);
    // 5: conv3 weight prep
    prep3_k<<<64, 256>>>(w3, w3p);
    // 6: skip = relu(BN2(x2)); dwt = Haar(skip)
    dwt_k<<<32768, 256>>>(x2, pg2, pbe2, s2, q2, skip, dwt);
    // 7: conv3
    convmma_k<256, 256, 256, false><<<dim3(8, 32, 4), 256, SMEM>>>(
        dwt, w3p, nullptr, s3, q3, y3);
    // 8: dwt_out = relu(BN3(y3))
    bn3relu_k<<<65536, 256>>>(y3, pg3, pbe3, s3, q3, dwt_out);
}

// round 6
// speedup vs baseline: 4.2484x; 1.0013x over previous
#include <cuda_runtime.h>
#include <math.h>
#include <stdint.h>

// ---------------- scratch buffers (device globals) ---------------------------
__device__ float g_x1[4ull*64*512*512];    // conv1 output (tf32-rounded)
__device__ float g_x2[4ull*64*512*512];    // conv2 raw output
__device__ float g_dwt[4ull*256*256*256];  // DWT of relu(BN2(x2)) (tf32-rounded)
__device__ float g_y3[4ull*64*256*256];    // conv3 raw output
__device__ __align__(16) float g_w2p[8*4608];    // conv2 weights, A-frag, *a1, rounded
__device__ __align__(16) float g_w3p[32*4608];   // conv3 weights, A-frag, rounded
__device__ float g_T[9*64];                // border bias table for conv2
__device__ float g_sum1[64], g_ss1[64];
__device__ float g_sum2[64], g_ss2[64];
__device__ float g_sum3[64], g_ss3[64];

#define EPSV 1e-5f
#define CI_STRIDE 344    // floats; 344 mod 32 = 24 -> tig offsets {0,24,16,8}: conflict-free

__device__ __forceinline__ float to_tf32(float f) {
    uint32_t r;
    asm("cvt.rna.tf32.f32 %0, %1;" : "=r"(r) : "f"(f));
    return __uint_as_float(r);
}

// ------ conv1: 3->64, 512x512 (tf32-rounded out) + fused stats-zero ----------
__global__ __launch_bounds__(256) void conv1_k(const float* __restrict__ in,
                                               const float* __restrict__ wg,
                                               float* __restrict__ out,
                                               float* __restrict__ z0,
                                               float* __restrict__ z1,
                                               float* __restrict__ z2,
                                               float* __restrict__ z3,
                                               float* __restrict__ z4,
                                               float* __restrict__ z5) {
    __shared__ __align__(16) float s_w[27][64];
    int tid = threadIdx.x;
    if (blockIdx.x == 0 && tid < 64) {
        z0[tid]=0.f; z1[tid]=0.f; z2[tid]=0.f; z3[tid]=0.f; z4[tid]=0.f; z5[tid]=0.f;
    }
    for (int idx = tid; idx < 27 * 64; idx += 256) {
        int co = idx & 63;
        int t  = idx >> 6;
        s_w[t][co] = wg[co * 27 + t];
    }
    __syncthreads();

    size_t pid = (size_t)blockIdx.x * 256 + tid;
    int w = (int)(pid & 511);
    int h = (int)((pid >> 9) & 511);
    int n = (int)(pid >> 18);

    const float* inp = in + (size_t)n * 3 * 512 * 512;
    float xv[27];
    int i = 0;
    #pragma unroll
    for (int ci = 0; ci < 3; ci++)
        #pragma unroll
        for (int kh = 0; kh < 3; kh++)
            #pragma unroll
            for (int kw = 0; kw < 3; kw++) {
                int hh = h + kh - 1, ww = w + kw - 1;
                xv[i++] = (hh >= 0 && hh < 512 && ww >= 0 && ww < 512)
                              ? __ldg(&inp[(size_t)ci * 512 * 512 + (size_t)hh * 512 + ww])
                              : 0.f;
            }

    size_t obase = ((size_t)n * 64) * (512 * 512) + (size_t)h * 512 + w;
    #pragma unroll 1
    for (int cog = 0; cog < 16; cog++) {
        float a0 = 0.f, a1 = 0.f, a2 = 0.f, a3 = 0.f;
        #pragma unroll
        for (int t = 0; t < 27; t++) {
            float4 w4 = *(const float4*)&s_w[t][cog * 4];
            a0 += xv[t] * w4.x;
            a1 += xv[t] * w4.y;
            a2 += xv[t] * w4.z;
            a3 += xv[t] * w4.w;
        }
        size_t ob = obase + (size_t)(cog * 4) * 512 * 512;
        out[ob]                    = to_tf32(a0);
        out[ob + 1ull*512*512]     = to_tf32(a1);
        out[ob + 2ull*512*512]     = to_tf32(a2);
        out[ob + 3ull*512*512]     = to_tf32(a3);
    }
}

// ---------------- stats over x1 (float4) -------------------------------------
__global__ void stats_k(const float* __restrict__ x, int HW,
                        float* __restrict__ sum, float* __restrict__ ss) {
    int c = blockIdx.x;
    float s = 0.f, q = 0.f;
    int stride = gridDim.y * blockDim.x;
    int start  = blockIdx.y * blockDim.x + threadIdx.x;
    int HW4 = HW >> 2;
    for (int n = 0; n < 4; n++) {
        const float4* p = (const float4*)(x + ((size_t)(n * 64 + c)) * HW);
        for (int i = start; i < HW4; i += stride) {
            float4 v = p[i];
            s += v.x + v.y + v.z + v.w;
            q += v.x * v.x + v.y * v.y + v.z * v.z + v.w * v.w;
        }
    }
    #pragma unroll
    for (int o = 16; o > 0; o >>= 1) {
        s += __shfl_down_sync(0xffffffffu, s, o);
        q += __shfl_down_sync(0xffffffffu, q, o);
    }
    __shared__ float bs[8], bq[8];
    int lane = threadIdx.x & 31, wid = threadIdx.x >> 5;
    if (lane == 0) { bs[wid] = s; bq[wid] = q; }
    __syncthreads();
    if (threadIdx.x < 8) {
        s = bs[threadIdx.x]; q = bq[threadIdx.x];
        #pragma unroll
        for (int o = 4; o > 0; o >>= 1) {
            s += __shfl_down_sync(0xffu, s, o);
            q += __shfl_down_sync(0xffu, q, o);
        }
        if (threadIdx.x == 0) { atomicAdd(&sum[c], s); atomicAdd(&ss[c], q); }
    }
}

// ---------------- prep3: w3 -> A-frag layout, tf32-rounded -------------------
__global__ __launch_bounds__(256) void prep3_k(const float* __restrict__ w3,
                                               float* __restrict__ wp) {
    for (int idx = blockIdx.x * 256 + threadIdx.x; idx < 32 * 4608;
         idx += gridDim.x * 256) {
        int chunk = idx / 4608;
        int rem   = idx - chunk * 4608;
        int tap   = rem >> 9;
        int cog   = (rem >> 7) & 3;
        int l     = (rem >> 2) & 31;
        int j     = rem & 3;
        int co = cog * 16 + (l >> 2) + ((j & 1) ? 8 : 0);
        int ci = chunk * 8 + (l & 3) + ((j & 2) ? 4 : 0);
        wp[idx] = to_tf32(__ldg(&w3[((size_t)co * 256 + ci) * 9 + tap]));
    }
}

// ------- prep2: BN1 finalize folded into w2 (A-frag layout) + border table ---
__global__ __launch_bounds__(256) void prep2_k(const float* __restrict__ w2,
                                               const float* __restrict__ g1,
                                               const float* __restrict__ be1,
                                               const float* __restrict__ sum1,
                                               const float* __restrict__ ss1,
                                               float* __restrict__ wp,
                                               float* __restrict__ Tt) {
    const float invM = 1.0f / (4.0f * 512.0f * 512.0f);
    for (int idx = blockIdx.x * 256 + threadIdx.x; idx < 8 * 4608;
         idx += gridDim.x * 256) {
        int chunk = idx / 4608;
        int rem   = idx - chunk * 4608;
        int tap   = rem >> 9;
        int cog   = (rem >> 7) & 3;
        int l     = (rem >> 2) & 31;
        int j     = rem & 3;
        int co = cog * 16 + (l >> 2) + ((j & 1) ? 8 : 0);
        int ci = chunk * 8 + (l & 3) + ((j & 2) ? 4 : 0);
        float mean = __ldg(&sum1[ci]) * invM;
        float var  = __ldg(&ss1[ci]) * invM - mean * mean;
        float a    = __ldg(&g1[ci]) * rsqrtf(var + EPSV);
        wp[idx] = to_tf32(__ldg(&w2[((size_t)co * 64 + ci) * 9 + tap]) * a);
    }
    if (blockIdx.x == 0) {
        for (int o = threadIdx.x; o < 9 * 64; o += 256) {
            int e  = o >> 6;
            int co = o & 63;
            int eh = e / 3, ew = e - eh * 3;
            int kh0 = (eh == 0) ? 1 : 0, kh1 = (eh == 2) ? 1 : 2;
            int kw0 = (ew == 0) ? 1 : 0, kw1 = (ew == 2) ? 1 : 2;
            float acc = 0.f;
            for (int ci = 0; ci < 64; ci++) {
                float mean = __ldg(&sum1[ci]) * invM;
                float var  = __ldg(&ss1[ci]) * invM - mean * mean;
                float a    = __ldg(&g1[ci]) * rsqrtf(var + EPSV);
                float b    = __ldg(&be1[ci]) - mean * a;
                float ws = 0.f;
                for (int kh = kh0; kh <= kh1; kh++)
                    for (int kw = kw0; kw <= kw1; kw++)
                        ws += __ldg(&w2[((size_t)co * 64 + ci) * 9 + kh * 3 + kw]);
                acc += b * ws;
            }
            Tt[o] = acc;
        }
    }
}

// ------- tf32 mma conv, 3-stage cp.async pipeline, 1 sync per chunk ----------
// dyn smem: s_in[3][2752] | s_wf[3][4608] | s_st[128]  = 88832 B
#define IN_SZ 2752
#define WF_SZ 4608

template <int C_IN, int H, int W, bool TT>
__global__ __launch_bounds__(256, 2) void convmma_k(const float* __restrict__ in,
                                                    const float* __restrict__ wp,
                                                    const float* __restrict__ Tt,
                                                    float* __restrict__ sum,
                                                    float* __restrict__ ss,
                                                    float* __restrict__ out) {
    extern __shared__ float smem[];
    float* s_in = smem;                        // 3 * 2752
    float* s_wf = smem + 3 * IN_SZ;            // 3 * 4608
    float* s_st = smem + 3 * IN_SZ + 3 * WF_SZ;// 128
    uint32_t sb_in = (uint32_t)__cvta_generic_to_shared(s_in);
    uint32_t sb_wf = (uint32_t)__cvta_generic_to_shared(s_wf);

    int n   = blockIdx.z;
    int th0 = blockIdx.y * 8;
    int tw0 = blockIdx.x * 32;
    int tid  = threadIdx.x;
    int warp = tid >> 5;
    int lane = tid & 31;
    int gid  = lane >> 2;
    int tig  = lane & 3;

    if (tid < 128) s_st[tid] = 0.f;

    float c[4][4][4];
    #pragma unroll
    for (int a = 0; a < 4; a++)
        #pragma unroll
        for (int b = 0; b < 4; b++)
            #pragma unroll
            for (int d = 0; d < 4; d++) c[a][b][d] = 0.f;

    const float* in_n = in + (size_t)n * C_IN * H * W;
    const int NCH = C_IN / 8;

    auto issue_chunk = [&](int chunk, int buf) {
        const float* gin = in_n + (size_t)chunk * 8 * H * W;
        #pragma unroll 1
        for (int idx = tid; idx < 2720; idx += 256) {
            int ci  = idx / 340;
            int rem = idx - ci * 340;
            int r   = rem / 34;
            int col = rem - r * 34;
            int gh = th0 + r - 1;
            int gw = tw0 + col - 1;
            bool ok = (gh >= 0 && gh < H && gw >= 0 && gw < W);
            const float* src = ok ? (gin + (size_t)ci * H * W + (size_t)gh * W + gw) : gin;
            uint32_t d = sb_in + (uint32_t)((buf * IN_SZ + ci * CI_STRIDE + r * 34 + col) * 4);
            int sz = ok ? 4 : 0;
            asm volatile("cp.async.ca.shared.global [%0], [%1], 4, %2;"
                         :: "r"(d), "l"(src), "r"(sz));
        }
        const float* wsrc = wp + (size_t)chunk * WF_SZ;
        #pragma unroll 1
        for (int i = tid; i < 1152; i += 256) {
            uint32_t d = sb_wf + (uint32_t)((buf * WF_SZ + i * 4) * 4);
            asm volatile("cp.async.cg.shared.global [%0], [%1], 16;"
                         :: "r"(d), "l"(wsrc + i * 4));
        }
        asm volatile("cp.async.commit_group;");
    };

    issue_chunk(0, 0);
    if (NCH > 1) issue_chunk(1, 1);

    int buf = 0;
    #pragma unroll 1
    for (int ch = 0; ch < NCH; ch++) {
        if (ch + 1 < NCH) {
            asm volatile("cp.async.wait_group 1;");
        } else {
            asm volatile("cp.async.wait_group 0;");
        }
        __syncthreads();
        if (ch + 2 < NCH) {
            int nbuf = buf + 2; if (nbuf >= 3) nbuf -= 3;
            issue_chunk(ch + 2, nbuf);
        }

        const float4* wf4 = (const float4*)(s_wf + buf * WF_SZ);
        const float*  sib = s_in + buf * IN_SZ;

        #pragma unroll
        for (int kh = 0; kh < 3; kh++) {
            #pragma unroll
            for (int kw = 0; kw < 3; kw++) {
                int tap = kh * 3 + kw;
                uint32_t A[4][4];
                #pragma unroll
                for (int cog = 0; cog < 4; cog++) {
                    float4 a4 = wf4[(tap * 4 + cog) * 32 + lane];
                    A[cog][0] = __float_as_uint(a4.x);
                    A[cog][1] = __float_as_uint(a4.y);
                    A[cog][2] = __float_as_uint(a4.z);
                    A[cog][3] = __float_as_uint(a4.w);
                }
                int rbase = (warp + kh) * 34;
                #pragma unroll
                for (int pf = 0; pf < 4; pf++) {
                    int col = pf * 8 + gid + kw;
                    uint32_t b0 = __float_as_uint(sib[tig * CI_STRIDE + rbase + col]);
                    uint32_t b1 = __float_as_uint(sib[(tig + 4) * CI_STRIDE + rbase + col]);
                    #pragma unroll
                    for (int cog = 0; cog < 4; cog++) {
                        asm volatile(
                            "mma.sync.aligned.m16n8k8.row.col.f32.tf32.tf32.f32 "
                            "{%0,%1,%2,%3}, {%4,%5,%6,%7}, {%8,%9}, {%0,%1,%2,%3};\n"
                            : "+f"(c[cog][pf][0]), "+f"(c[cog][pf][1]),
                              "+f"(c[cog][pf][2]), "+f"(c[cog][pf][3])
                            : "r"(A[cog][0]), "r"(A[cog][1]), "r"(A[cog][2]), "r"(A[cog][3]),
                              "r"(b0), "r"(b1));
                    }
                }
            }
        }
        buf++; if (buf >= 3) buf = 0;
    }

    // ---- epilogue: optional border-bias, stores, fused stats ----
    int h = th0 + warp;
    float* op = out + ((size_t)n * 64) * H * W + (size_t)h * W + tw0;
    int eh = (h == 0) ? 0 : ((h == H - 1) ? 2 : 1);
    float csum[8], csq[8];
    #pragma unroll
    for (int q = 0; q < 8; q++) { csum[q] = 0.f; csq[q] = 0.f; }

    #pragma unroll
    for (int cog = 0; cog < 4; cog++) {
        int coA = cog * 16 + gid;
        int coB = coA + 8;
        #pragma unroll
        for (int pf = 0; pf < 4; pf++) {
            int w0 = tw0 + pf * 8 + tig * 2;
            float v0 = c[cog][pf][0], v1 = c[cog][pf][1];
            float v2 = c[cog][pf][2], v3 = c[cog][pf][3];
            if (TT) {
                int ew0 = (w0 == 0) ? 0 : ((w0 == W - 1) ? 2 : 1);
                int ew1 = ((w0 + 1) == W - 1) ? 2 : 1;
                v0 += __ldg(&Tt[(eh * 3 + ew0) * 64 + coA]);
                v1 += __ldg(&Tt[(eh * 3 + ew1) * 64 + coA]);
                v2 += __ldg(&Tt[(eh * 3 + ew0) * 64 + coB]);
                v3 += __ldg(&Tt[(eh * 3 + ew1) * 64 + coB]);
            }
            *(float2*)(op + (size_t)coA * H * W + pf * 8 + tig * 2) = make_float2(v0, v1);
            *(float2*)(op + (size_t)coB * H * W + pf * 8 + tig * 2) = make_float2(v2, v3);
            csum[cog * 2]     += v0 + v1;
            csq[cog * 2]      += v0 * v0 + v1 * v1;
            csum[cog * 2 + 1] += v2 + v3;
            csq[cog * 2 + 1]  += v2 * v2 + v3 * v3;
        }
    }
    #pragma unroll
    for (int q = 0; q < 8; q++) {
        int co = (q >> 1) * 16 + gid + ((q & 1) ? 8 : 0);
        atomicAdd(&s_st[co], csum[q]);
        atomicAdd(&s_st[64 + co], csq[q]);
    }
    __syncthreads();
    if (tid < 64) {
        atomicAdd(&sum[tid], s_st[tid]);
        atomicAdd(&ss[tid], s_st[64 + tid]);
    }
}

// -------- BN2 (inline finalize) + relu -> skip; Haar DWT (rounded) -> g_dwt --
__global__ __launch_bounds__(256) void dwt_k(const float* __restrict__ x2,
                                             const float* __restrict__ g2,
                                             const float* __restrict__ be2,
                                             const float* __restrict__ sum2,
                                             const float* __restrict__ ss2,
                                             float* __restrict__ skip,
                                             float* __restrict__ dwt) {
    size_t idx = (size_t)blockIdx.x * 256 + threadIdx.x;
    int wp = (int)(idx & 127);
    int h2 = (int)((idx >> 7) & 255);
    int c  = (int)((idx >> 15) & 63);
    int n  = (int)(idx >> 21);

    const float invM = 1.0f / (4.0f * 512.0f * 512.0f);
    float mean = __ldg(&sum2[c]) * invM;
    float var  = __ldg(&ss2[c]) * invM - mean * mean;
    float a    = __ldg(&g2[c]) * rsqrtf(var + EPSV);
    float b    = __ldg(&be2[c]) - mean * a;

    size_t ibase = ((size_t)(n * 64 + c)) * 512 * 512 + (size_t)(2 * h2) * 512 + wp * 4;
    float4 r0 = *(const float4*)(x2 + ibase);
    float4 r1 = *(const float4*)(x2 + ibase + 512);
    r0.x = fmaxf(fmaf(r0.x, a, b), 0.f);
    r0.y = fmaxf(fmaf(r0.y, a, b), 0.f);
    r0.z = fmaxf(fmaf(r0.z, a, b), 0.f);
    r0.w = fmaxf(fmaf(r0.w, a, b), 0.f);
    r1.x = fmaxf(fmaf(r1.x, a, b), 0.f);
    r1.y = fmaxf(fmaf(r1.y, a, b), 0.f);
    r1.z = fmaxf(fmaf(r1.z, a, b), 0.f);
    r1.w = fmaxf(fmaf(r1.w, a, b), 0.f);

    *(float4*)(skip + ibase)       = r0;
    *(float4*)(skip + ibase + 512) = r1;

    size_t dbase = ((size_t)(n * 256 + c)) * 256 * 256 + (size_t)h2 * 256 + wp * 2;
    const size_t CH = (size_t)64 * 256 * 256;

    float cA0 = (r0.x + r0.y + r1.x + r1.y) * 0.5f;
    float cH0 = (r0.x + r0.y - r1.x - r1.y) * 0.5f;
    float cV0 = (r0.x - r0.y + r1.x - r1.y) * 0.5f;
    float cD0 = (r0.x - r0.y - r1.x + r1.y) * 0.5f;
    float cA1 = (r0.z + r0.w + r1.z + r1.w) * 0.5f;
    float cH1 = (r0.z + r0.w - r1.z - r1.w) * 0.5f;
    float cV1 = (r0.z - r0.w + r1.z - r1.w) * 0.5f;
    float cD1 = (r0.z - r0.w - r1.z + r1.w) * 0.5f;

    *(float2*)(dwt + dbase)          = make_float2(to_tf32(cA0), to_tf32(cA1));
    *(float2*)(dwt + dbase + CH)     = make_float2(to_tf32(cH0), to_tf32(cH1));
    *(float2*)(dwt + dbase + 2 * CH) = make_float2(to_tf32(cV0), to_tf32(cV1));
    *(float2*)(dwt + dbase + 3 * CH) = make_float2(to_tf32(cD0), to_tf32(cD1));
}

// -------- BN3 (inline finalize) + relu -> dwt_out ----------------------------
__global__ __launch_bounds__(256) void bn3relu_k(const float* __restrict__ y3,
                                                 const float* __restrict__ g3,
                                                 const float* __restrict__ be3,
                                                 const float* __restrict__ sum3,
                                                 const float* __restrict__ ss3,
                                                 float* __restrict__ out) {
    size_t idx = (size_t)blockIdx.x * 256 + threadIdx.x;
    int c = (int)((idx >> 16) & 63);
    const float invM = 1.0f / (4.0f * 256.0f * 256.0f);
    float mean = __ldg(&sum3[c]) * invM;
    float var  = __ldg(&ss3[c]) * invM - mean * mean;
    float a    = __ldg(&g3[c]) * rsqrtf(var + EPSV);
    float b    = __ldg(&be3[c]) - mean * a;
    out[idx] = fmaxf(fmaf(y3[idx], a, b), 0.f);
}

// ---------------- host orchestration ----------------------------------------
extern "C" void kernel_launch(void* const* d_in, const int* in_sizes, int n_in,
                              void* d_out, int out_size) {
    const float* inp  = (const float*)d_in[0];
    const float* w1   = (const float*)d_in[1];
    const float* pg1  = (const float*)d_in[3];
    const float* pbe1 = (const float*)d_in[4];
    const float* w2   = (const float*)d_in[5];
    const float* pg2  = (const float*)d_in[7];
    const float* pbe2 = (const float*)d_in[8];
    const float* w3   = (const float*)d_in[9];
    const float* pg3  = (const float*)d_in[11];
    const float* pbe3 = (const float*)d_in[12];

    float* out     = (float*)d_out;
    float* dwt_out = out;
    float* skip    = out + 16777216ull;

    float *x1, *x2, *dwt, *y3, *w2p, *w3p, *Tt;
    float *s1, *q1, *s2, *q2, *s3, *q3;
    cudaGetSymbolAddress((void**)&x1,  g_x1);
    cudaGetSymbolAddress((void**)&x2,  g_x2);
    cudaGetSymbolAddress((void**)&dwt, g_dwt);
    cudaGetSymbolAddress((void**)&y3,  g_y3);
    cudaGetSymbolAddress((void**)&w2p, g_w2p);
    cudaGetSymbolAddress((void**)&w3p, g_w3p);
    cudaGetSymbolAddress((void**)&Tt,  g_T);
    cudaGetSymbolAddress((void**)&s1,  g_sum1);
    cudaGetSymbolAddress((void**)&q1,  g_ss1);
    cudaGetSymbolAddress((void**)&s2,  g_sum2);
    cudaGetSymbolAddress((void**)&q2,  g_ss2);
    cudaGetSymbolAddress((void**)&s3,  g_sum3);
    cudaGetSymbolAddress((void**)&q3,  g_ss3);

    const int SMEM = (3 * IN_SZ + 3 * WF_SZ + 128) * 4;  // 88832 B
    cudaFuncSetAttribute(convmma_k<64, 512, 512, true>,
                         cudaFuncAttributeMaxDynamicSharedMemorySize, SMEM);
    cudaFuncSetAttribute(convmma_k<256, 256, 256, false>,
                         cudaFuncAttributeMaxDynamicSharedMemorySize, SMEM);

    // 1: conv1 (+ zero all stats)
    conv1_k<<<4096, 256>>>(inp, w1, x1, s1, q1, s2, q2, s3, q3);
    // 2: BN1 stats
    stats_k<<<dim3(64, 32), 256>>>(x1, 512 * 512, s1, q1);
    // 3: fold BN1 into conv2 weights + border table
    prep2_k<<<64, 256>>>(w2, pg1, pbe1, s1, q1, w2p, Tt);
    // 4: conv2  <- ncu profiles launch #4
    convmma_k<64, 512, 512, true><<<dim3(16, 64, 4), 256, SMEM>>>(
        x1, w2p, Tt, s2, q2, x2);
    // 5: conv3 weight prep
    prep3_k<<<64, 256>>>(w3, w3p);
    // 6: skip = relu(BN2(x2)); dwt = Haar(skip)
    dwt_k<<<32768, 256>>>(x2, pg2, pbe2, s2, q2, skip, dwt);
    // 7: conv3
    convmma_k<256, 256, 256, false><<<dim3(8, 32, 4), 256, SMEM>>>(
        dwt, w3p, nullptr, s3, q3, y3);
    // 8: dwt_out = relu(BN3(y3))
    bn3relu_k<<<65536, 256>>>(y3, pg3, pbe3, s3, q3, dwt_out);
}

// round 7
// speedup vs baseline: 4.6405x; 1.0923x over previous
#include <cuda_runtime.h>
#include <math.h>
#include <stdint.h>

// ---------------- scratch buffers (device globals) ---------------------------
__device__ float g_x1[4ull*64*512*512];    // conv1 output (tf32-rounded)
__device__ float g_x2[4ull*64*512*512];    // conv2 raw output
__device__ float g_dwt[4ull*256*256*256];  // DWT of relu(BN2(x2)) (tf32-rounded)
__device__ float g_y3[4ull*64*256*256];    // conv3 raw output
__device__ __align__(16) float g_w2p[8*4608];    // conv2 weights, A-frag, *a1, rounded
__device__ __align__(16) float g_w3p[32*4608];   // conv3 weights, A-frag, rounded
__device__ float g_T[9*64];                // border bias table for conv2
__device__ float g_sum1[64], g_ss1[64];
__device__ float g_sum2[64], g_ss2[64];
__device__ float g_sum3[64], g_ss3[64];

#define EPSV 1e-5f
// input tile: 8 ci x 18 rows x (row stride 40).  cols: 3=left halo, 4..35 interior, 36=right halo
#define ROWST 40
#define CI_ST 728        // 18*40=720 -> 728; 728 mod 32 = 24 -> tig banks {0,24,16,8} distinct
#define IN_SZ 5824       // 8 * 728 floats per buffer
#define WF_SZ 4608

__device__ __forceinline__ float to_tf32(float f) {
    uint32_t r;
    asm("cvt.rna.tf32.f32 %0, %1;" : "=r"(r) : "f"(f));
    return __uint_as_float(r);
}

// ------ conv1: 3->64, 512x512 (tf32-rounded out) + fused stats-zero ----------
__global__ __launch_bounds__(256) void conv1_k(const float* __restrict__ in,
                                               const float* __restrict__ wg,
                                               float* __restrict__ out,
                                               float* __restrict__ z0,
                                               float* __restrict__ z1,
                                               float* __restrict__ z2,
                                               float* __restrict__ z3,
                                               float* __restrict__ z4,
                                               float* __restrict__ z5) {
    __shared__ __align__(16) float s_w[27][64];
    int tid = threadIdx.x;
    if (blockIdx.x == 0 && tid < 64) {
        z0[tid]=0.f; z1[tid]=0.f; z2[tid]=0.f; z3[tid]=0.f; z4[tid]=0.f; z5[tid]=0.f;
    }
    for (int idx = tid; idx < 27 * 64; idx += 256) {
        int co = idx & 63;
        int t  = idx >> 6;
        s_w[t][co] = wg[co * 27 + t];
    }
    __syncthreads();

    size_t pid = (size_t)blockIdx.x * 256 + tid;
    int w = (int)(pid & 511);
    int h = (int)((pid >> 9) & 511);
    int n = (int)(pid >> 18);

    const float* inp = in + (size_t)n * 3 * 512 * 512;
    float xv[27];
    int i = 0;
    #pragma unroll
    for (int ci = 0; ci < 3; ci++)
        #pragma unroll
        for (int kh = 0; kh < 3; kh++)
            #pragma unroll
            for (int kw = 0; kw < 3; kw++) {
                int hh = h + kh - 1, ww = w + kw - 1;
                xv[i++] = (hh >= 0 && hh < 512 && ww >= 0 && ww < 512)
                              ? __ldg(&inp[(size_t)ci * 512 * 512 + (size_t)hh * 512 + ww])
                              : 0.f;
            }

    size_t obase = ((size_t)n * 64) * (512 * 512) + (size_t)h * 512 + w;
    #pragma unroll 1
    for (int cog = 0; cog < 16; cog++) {
        float a0 = 0.f, a1 = 0.f, a2 = 0.f, a3 = 0.f;
        #pragma unroll
        for (int t = 0; t < 27; t++) {
            float4 w4 = *(const float4*)&s_w[t][cog * 4];
            a0 += xv[t] * w4.x;
            a1 += xv[t] * w4.y;
            a2 += xv[t] * w4.z;
            a3 += xv[t] * w4.w;
        }
        size_t ob = obase + (size_t)(cog * 4) * 512 * 512;
        out[ob]                = to_tf32(a0);
        out[ob + 1ull*512*512] = to_tf32(a1);
        out[ob + 2ull*512*512] = to_tf32(a2);
        out[ob + 3ull*512*512] = to_tf32(a3);
    }
}

// ---------------- stats over x1 (float4) -------------------------------------
__global__ void stats_k(const float* __restrict__ x, int HW,
                        float* __restrict__ sum, float* __restrict__ ss) {
    int c = blockIdx.x;
    float s = 0.f, q = 0.f;
    int stride = gridDim.y * blockDim.x;
    int start  = blockIdx.y * blockDim.x + threadIdx.x;
    int HW4 = HW >> 2;
    for (int n = 0; n < 4; n++) {
        const float4* p = (const float4*)(x + ((size_t)(n * 64 + c)) * HW);
        for (int i = start; i < HW4; i += stride) {
            float4 v = p[i];
            s += v.x + v.y + v.z + v.w;
            q += v.x * v.x + v.y * v.y + v.z * v.z + v.w * v.w;
        }
    }
    #pragma unroll
    for (int o = 16; o > 0; o >>= 1) {
        s += __shfl_down_sync(0xffffffffu, s, o);
        q += __shfl_down_sync(0xffffffffu, q, o);
    }
    __shared__ float bs[8], bq[8];
    int lane = threadIdx.x & 31, wid = threadIdx.x >> 5;
    if (lane == 0) { bs[wid] = s; bq[wid] = q; }
    __syncthreads();
    if (threadIdx.x < 8) {
        s = bs[threadIdx.x]; q = bq[threadIdx.x];
        #pragma unroll
        for (int o = 4; o > 0; o >>= 1) {
            s += __shfl_down_sync(0xffu, s, o);
            q += __shfl_down_sync(0xffu, q, o);
        }
        if (threadIdx.x == 0) { atomicAdd(&sum[c], s); atomicAdd(&ss[c], q); }
    }
}

// ---------------- prep3: w3 -> A-frag layout, tf32-rounded -------------------
__global__ __launch_bounds__(256) void prep3_k(const float* __restrict__ w3,
                                               float* __restrict__ wp) {
    for (int idx = blockIdx.x * 256 + threadIdx.x; idx < 32 * 4608;
         idx += gridDim.x * 256) {
        int chunk = idx / 4608;
        int rem   = idx - chunk * 4608;
        int tap   = rem >> 9;
        int cog   = (rem >> 7) & 3;
        int l     = (rem >> 2) & 31;
        int j     = rem & 3;
        int co = cog * 16 + (l >> 2) + ((j & 1) ? 8 : 0);
        int ci = chunk * 8 + (l & 3) + ((j & 2) ? 4 : 0);
        wp[idx] = to_tf32(__ldg(&w3[((size_t)co * 256 + ci) * 9 + tap]));
    }
}

// ------- prep2: BN1 finalize folded into w2 (A-frag layout) + border table ---
__global__ __launch_bounds__(256) void prep2_k(const float* __restrict__ w2,
                                               const float* __restrict__ g1,
                                               const float* __restrict__ be1,
                                               const float* __restrict__ sum1,
                                               const float* __restrict__ ss1,
                                               float* __restrict__ wp,
                                               float* __restrict__ Tt) {
    const float invM = 1.0f / (4.0f * 512.0f * 512.0f);
    for (int idx = blockIdx.x * 256 + threadIdx.x; idx < 8 * 4608;
         idx += gridDim.x * 256) {
        int chunk = idx / 4608;
        int rem   = idx - chunk * 4608;
        int tap   = rem >> 9;
        int cog   = (rem >> 7) & 3;
        int l     = (rem >> 2) & 31;
        int j     = rem & 3;
        int co = cog * 16 + (l >> 2) + ((j & 1) ? 8 : 0);
        int ci = chunk * 8 + (l & 3) + ((j & 2) ? 4 : 0);
        float mean = __ldg(&sum1[ci]) * invM;
        float var  = __ldg(&ss1[ci]) * invM - mean * mean;
        float a    = __ldg(&g1[ci]) * rsqrtf(var + EPSV);
        wp[idx] = to_tf32(__ldg(&w2[((size_t)co * 64 + ci) * 9 + tap]) * a);
    }
    if (blockIdx.x == 0) {
        for (int o = threadIdx.x; o < 9 * 64; o += 256) {
            int e  = o >> 6;
            int co = o & 63;
            int eh = e / 3, ew = e - eh * 3;
            int kh0 = (eh == 0) ? 1 : 0, kh1 = (eh == 2) ? 1 : 2;
            int kw0 = (ew == 0) ? 1 : 0, kw1 = (ew == 2) ? 1 : 2;
            float acc = 0.f;
            for (int ci = 0; ci < 64; ci++) {
                float mean = __ldg(&sum1[ci]) * invM;
                float var  = __ldg(&ss1[ci]) * invM - mean * mean;
                float a    = __ldg(&g1[ci]) * rsqrtf(var + EPSV);
                float b    = __ldg(&be1[ci]) - mean * a;
                float ws = 0.f;
                for (int kh = kh0; kh <= kh1; kh++)
                    for (int kw = kw0; kw <= kw1; kw++)
                        ws += __ldg(&w2[((size_t)co * 64 + ci) * 9 + kh * 3 + kw]);
                acc += b * ws;
            }
            Tt[o] = acc;
        }
    }
}

// ------- tf32 mma conv: 16h x 32w x 64co tile, 512 thr, vectorized cp.async --
// dyn smem: s_in[3][IN_SZ] | s_wf[3][WF_SZ] | s_st[128]
template <int C_IN, int H, int W, bool TT>
__global__ __launch_bounds__(512, 1) void convmma_k(const float* __restrict__ in,
                                                    const float* __restrict__ wp,
                                                    const float* __restrict__ Tt,
                                                    float* __restrict__ sum,
                                                    float* __restrict__ ss,
                                                    float* __restrict__ out) {
    extern __shared__ float smem[];
    float* s_in = smem;                        // 3 * IN_SZ
    float* s_wf = smem + 3 * IN_SZ;            // 3 * WF_SZ
    float* s_st = smem + 3 * IN_SZ + 3 * WF_SZ;// 128
    uint32_t sb_in = (uint32_t)__cvta_generic_to_shared(s_in);
    uint32_t sb_wf = (uint32_t)__cvta_generic_to_shared(s_wf);

    int n   = blockIdx.z;
    int th0 = blockIdx.y * 16;
    int tw0 = blockIdx.x * 32;
    int tid  = threadIdx.x;
    int warp = tid >> 5;       // 0..15 -> output row
    int lane = tid & 31;
    int gid  = lane >> 2;
    int tig  = lane & 3;

    if (tid < 128) s_st[tid] = 0.f;

    const float* in_n = in + (size_t)n * C_IN * H * W;
    const int NCH = C_IN / 8;
    const size_t CHSTEP = (size_t)8 * H * W;   // floats per ci-chunk

    // ---- precompute staging slots (constant across chunks) ----
    // interior: 1152 16B ops: o = tid + 512k, k=0..2
    const float* i_src[3];
    uint32_t     i_dst[3];
    bool         i_ok[3];
    #pragma unroll
    for (int k = 0; k < 3; k++) {
        int o = tid + 512 * k;
        if (o < 1152) {
            int q   = o & 7;
            int rid = o >> 3;          // 0..143
            int ci  = rid / 18;
            int r   = rid - ci * 18;
            int gh  = th0 + r - 1;
            i_ok[k]  = (gh >= 0 && gh < H);
            i_src[k] = in_n + (size_t)ci * H * W + (size_t)(i_ok[k] ? gh : 0) * W + tw0 + q * 4;
            i_dst[k] = sb_in + (uint32_t)((ci * CI_ST + r * ROWST + 4 + q * 4) * 4);
        } else {
            i_ok[k] = false; i_src[k] = in_n; i_dst[k] = sb_in; // never issued
        }
    }
    bool i_has[3] = { true, true, tid < 128 };
    // halo: 288 scalar ops (tid < 288)
    const float* h_src = in_n;
    uint32_t     h_dst = sb_in;
    bool         h_ok  = false;
    bool         h_has = (tid < 288);
    if (h_has) {
        int ci   = tid / 36;
        int rem  = tid - ci * 36;
        int r    = rem >> 1;
        int side = rem & 1;
        int gh   = th0 + r - 1;
        int gw   = side ? (tw0 + 32) : (tw0 - 1);
        int col  = side ? 36 : 3;
        h_ok  = (gh >= 0 && gh < H && gw >= 0 && gw < W);
        h_src = in_n + (size_t)ci * H * W + (size_t)(h_ok ? gh : 0) * W + (h_ok ? gw : 0);
        h_dst = sb_in + (uint32_t)((ci * CI_ST + r * ROWST + col) * 4);
    }
    // weights: 1152 16B ops: o = tid + 512k, k=0..2 (k=2: tid<128)
    const float* w_base = wp + (size_t)tid * 4;

    auto issue_chunk = [&](int chunk, int buf) {
        size_t cofs = (size_t)chunk * CHSTEP;
        uint32_t bofs = (uint32_t)(buf * IN_SZ * 4);
        #pragma unroll
        for (int k = 0; k < 3; k++) {
            if (i_has[k]) {
                int sz = i_ok[k] ? 16 : 0;
                asm volatile("cp.async.cg.shared.global [%0], [%1], 16, %2;"
                             :: "r"(i_dst[k] + bofs), "l"(i_src[k] + cofs), "r"(sz));
            }
        }
        if (h_has) {
            int sz = h_ok ? 4 : 0;
            asm volatile("cp.async.ca.shared.global [%0], [%1], 4, %2;"
                         :: "r"(h_dst + bofs), "l"(h_src + cofs), "r"(sz));
        }
        const float* wsrc = w_base + (size_t)chunk * WF_SZ;
        uint32_t wdst = sb_wf + (uint32_t)(buf * WF_SZ * 4) + (uint32_t)tid * 16;
        asm volatile("cp.async.cg.shared.global [%0], [%1], 16;"
                     :: "r"(wdst), "l"(wsrc));
        asm volatile("cp.async.cg.shared.global [%0], [%1], 16;"
                     :: "r"(wdst + 512 * 16), "l"(wsrc + 512 * 4));
        if (tid < 128)
            asm volatile("cp.async.cg.shared.global [%0], [%1], 16;"
                         :: "r"(wdst + 1024 * 16), "l"(wsrc + 1024 * 4));
        asm volatile("cp.async.commit_group;");
    };

    float c[4][4][4];
    #pragma unroll
    for (int a = 0; a < 4; a++)
        #pragma unroll
        for (int b = 0; b < 4; b++)
            #pragma unroll
            for (int d = 0; d < 4; d++) c[a][b][d] = 0.f;

    issue_chunk(0, 0);
    if (NCH > 1) issue_chunk(1, 1);

    int buf = 0;
    #pragma unroll 1
    for (int ch = 0; ch < NCH; ch++) {
        if (ch + 1 < NCH) {
            asm volatile("cp.async.wait_group 1;");
        } else {
            asm volatile("cp.async.wait_group 0;");
        }
        __syncthreads();
        if (ch + 2 < NCH) {
            int nbuf = buf + 2; if (nbuf >= 3) nbuf -= 3;
            issue_chunk(ch + 2, nbuf);
        }

        const float4* wf4 = (const float4*)(s_wf + buf * WF_SZ);
        const float*  sib = s_in + buf * IN_SZ;

        #pragma unroll
        for (int kh = 0; kh < 3; kh++) {
            #pragma unroll
            for (int kw = 0; kw < 3; kw++) {
                int tap = kh * 3 + kw;
                uint32_t A[4][4];
                #pragma unroll
                for (int cog = 0; cog < 4; cog++) {
                    float4 a4 = wf4[(tap * 4 + cog) * 32 + lane];
                    A[cog][0] = __float_as_uint(a4.x);
                    A[cog][1] = __float_as_uint(a4.y);
                    A[cog][2] = __float_as_uint(a4.z);
                    A[cog][3] = __float_as_uint(a4.w);
                }
                int rbase = (warp + kh) * ROWST + kw + 3;
                #pragma unroll
                for (int pf = 0; pf < 4; pf++) {
                    int col = rbase + pf * 8 + gid;
                    uint32_t b0 = __float_as_uint(sib[tig * CI_ST + col]);
                    uint32_t b1 = __float_as_uint(sib[(tig + 4) * CI_ST + col]);
                    #pragma unroll
                    for (int cog = 0; cog < 4; cog++) {
                        asm volatile(
                            "mma.sync.aligned.m16n8k8.row.col.f32.tf32.tf32.f32 "
                            "{%0,%1,%2,%3}, {%4,%5,%6,%7}, {%8,%9}, {%0,%1,%2,%3};\n"
                            : "+f"(c[cog][pf][0]), "+f"(c[cog][pf][1]),
                              "+f"(c[cog][pf][2]), "+f"(c[cog][pf][3])
                            : "r"(A[cog][0]), "r"(A[cog][1]), "r"(A[cog][2]), "r"(A[cog][3]),
                              "r"(b0), "r"(b1));
                    }
                }
            }
        }
        buf++; if (buf >= 3) buf = 0;
    }

    // ---- epilogue: optional border-bias, stores, fused stats ----
    int h = th0 + warp;
    float* op = out + ((size_t)n * 64) * H * W + (size_t)h * W + tw0;
    int eh = (h == 0) ? 0 : ((h == H - 1) ? 2 : 1);
    float csum[8], csq[8];
    #pragma unroll
    for (int q = 0; q < 8; q++) { csum[q] = 0.f; csq[q] = 0.f; }

    #pragma unroll
    for (int cog = 0; cog < 4; cog++) {
        int coA = cog * 16 + gid;
        int coB = coA + 8;
        #pragma unroll
        for (int pf = 0; pf < 4; pf++) {
            int w0 = tw0 + pf * 8 + tig * 2;
            float v0 = c[cog][pf][0], v1 = c[cog][pf][1];
            float v2 = c[cog][pf][2], v3 = c[cog][pf][3];
            if (TT) {
                int ew0 = (w0 == 0) ? 0 : ((w0 == W - 1) ? 2 : 1);
                int ew1 = ((w0 + 1) == W - 1) ? 2 : 1;
                v0 += __ldg(&Tt[(eh * 3 + ew0) * 64 + coA]);
                v1 += __ldg(&Tt[(eh * 3 + ew1) * 64 + coA]);
                v2 += __ldg(&Tt[(eh * 3 + ew0) * 64 + coB]);
                v3 += __ldg(&Tt[(eh * 3 + ew1) * 64 + coB]);
            }
            *(float2*)(op + (size_t)coA * H * W + pf * 8 + tig * 2) = make_float2(v0, v1);
            *(float2*)(op + (size_t)coB * H * W + pf * 8 + tig * 2) = make_float2(v2, v3);
            csum[cog * 2]     += v0 + v1;
            csq[cog * 2]      += v0 * v0 + v1 * v1;
            csum[cog * 2 + 1] += v2 + v3;
            csq[cog * 2 + 1]  += v2 * v2 + v3 * v3;
        }
    }
    #pragma unroll
    for (int q = 0; q < 8; q++) {
        int co = (q >> 1) * 16 + gid + ((q & 1) ? 8 : 0);
        atomicAdd(&s_st[co], csum[q]);
        atomicAdd(&s_st[64 + co], csq[q]);
    }
    __syncthreads();
    if (tid < 64) {
        atomicAdd(&sum[tid], s_st[tid]);
        atomicAdd(&ss[tid], s_st[64 + tid]);
    }
}

// -------- BN2 (inline finalize) + relu -> skip; Haar DWT (rounded) -> g_dwt --
__global__ __launch_bounds__(256) void dwt_k(const float* __restrict__ x2,
                                             const float* __restrict__ g2,
                                             const float* __restrict__ be2,
                                             const float* __restrict__ sum2,
                                             const float* __restrict__ ss2,
                                             float* __restrict__ skip,
                                             float* __restrict__ dwt) {
    size_t idx = (size_t)blockIdx.x * 256 + threadIdx.x;
    int wp = (int)(idx & 127);
    int h2 = (int)((idx >> 7) & 255);
    int c  = (int)((idx >> 15) & 63);
    int n  = (int)(idx >> 21);

    const float invM = 1.0f / (4.0f * 512.0f * 512.0f);
    float mean = __ldg(&sum2[c]) * invM;
    float var  = __ldg(&ss2[c]) * invM - mean * mean;
    float a    = __ldg(&g2[c]) * rsqrtf(var + EPSV);
    float b    = __ldg(&be2[c]) - mean * a;

    size_t ibase = ((size_t)(n * 64 + c)) * 512 * 512 + (size_t)(2 * h2) * 512 + wp * 4;
    float4 r0 = *(const float4*)(x2 + ibase);
    float4 r1 = *(const float4*)(x2 + ibase + 512);
    r0.x = fmaxf(fmaf(r0.x, a, b), 0.f);
    r0.y = fmaxf(fmaf(r0.y, a, b), 0.f);
    r0.z = fmaxf(fmaf(r0.z, a, b), 0.f);
    r0.w = fmaxf(fmaf(r0.w, a, b), 0.f);
    r1.x = fmaxf(fmaf(r1.x, a, b), 0.f);
    r1.y = fmaxf(fmaf(r1.y, a, b), 0.f);
    r1.z = fmaxf(fmaf(r1.z, a, b), 0.f);
    r1.w = fmaxf(fmaf(r1.w, a, b), 0.f);

    *(float4*)(skip + ibase)       = r0;
    *(float4*)(skip + ibase + 512) = r1;

    size_t dbase = ((size_t)(n * 256 + c)) * 256 * 256 + (size_t)h2 * 256 + wp * 2;
    const size_t CH = (size_t)64 * 256 * 256;

    float cA0 = (r0.x + r0.y + r1.x + r1.y) * 0.5f;
    float cH0 = (r0.x + r0.y - r1.x - r1.y) * 0.5f;
    float cV0 = (r0.x - r0.y + r1.x - r1.y) * 0.5f;
    float cD0 = (r0.x - r0.y - r1.x + r1.y) * 0.5f;
    float cA1 = (r0.z + r0.w + r1.z + r1.w) * 0.5f;
    float cH1 = (r0.z + r0.w - r1.z - r1.w) * 0.5f;
    float cV1 = (r0.z - r0.w + r1.z - r1.w) * 0.5f;
    float cD1 = (r0.z - r0.w - r1.z + r1.w) * 0.5f;

    *(float2*)(dwt + dbase)          = make_float2(to_tf32(cA0), to_tf32(cA1));
    *(float2*)(dwt + dbase + CH)     = make_float2(to_tf32(cH0), to_tf32(cH1));
    *(float2*)(dwt + dbase + 2 * CH) = make_float2(to_tf32(cV0), to_tf32(cV1));
    *(float2*)(dwt + dbase + 3 * CH) = make_float2(to_tf32(cD0), to_tf32(cD1));
}

// -------- BN3 (inline finalize) + relu -> dwt_out ----------------------------
__global__ __launch_bounds__(256) void bn3relu_k(const float* __restrict__ y3,
                                                 const float* __restrict__ g3,
                                                 const float* __restrict__ be3,
                                                 const float* __restrict__ sum3,
                                                 const float* __restrict__ ss3,
                                                 float* __restrict__ out) {
    size_t idx = (size_t)blockIdx.x * 256 + threadIdx.x;
    int c = (int)((idx >> 16) & 63);
    const float invM = 1.0f / (4.0f * 256.0f * 256.0f);
    float mean = __ldg(&sum3[c]) * invM;
    float var  = __ldg(&ss3[c]) * invM - mean * mean;
    float a    = __ldg(&g3[c]) * rsqrtf(var + EPSV);
    float b    = __ldg(&be3[c]) - mean * a;
    out[idx] = fmaxf(fmaf(y3[idx], a, b), 0.f);
}

// ---------------- host orchestration ----------------------------------------
extern "C" void kernel_launch(void* const* d_in, const int* in_sizes, int n_in,
                              void* d_out, int out_size) {
    const float* inp  = (const float*)d_in[0];
    const float* w1   = (const float*)d_in[1];
    const float* pg1  = (const float*)d_in[3];
    const float* pbe1 = (const float*)d_in[4];
    const float* w2   = (const float*)d_in[5];
    const float* pg2  = (const float*)d_in[7];
    const float* pbe2 = (const float*)d_in[8];
    const float* w3   = (const float*)d_in[9];
    const float* pg3  = (const float*)d_in[11];
    const float* pbe3 = (const float*)d_in[12];

    float* out     = (float*)d_out;
    float* dwt_out = out;
    float* skip    = out + 16777216ull;

    float *x1, *x2, *dwt, *y3, *w2p, *w3p, *Tt;
    float *s1, *q1, *s2, *q2, *s3, *q3;
    cudaGetSymbolAddress((void**)&x1,  g_x1);
    cudaGetSymbolAddress((void**)&x2,  g_x2);
    cudaGetSymbolAddress((void**)&dwt, g_dwt);
    cudaGetSymbolAddress((void**)&y3,  g_y3);
    cudaGetSymbolAddress((void**)&w2p, g_w2p);
    cudaGetSymbolAddress((void**)&w3p, g_w3p);
    cudaGetSymbolAddress((void**)&Tt,  g_T);
    cudaGetSymbolAddress((void**)&s1,  g_sum1);
    cudaGetSymbolAddress((void**)&q1,  g_ss1);
    cudaGetSymbolAddress((void**)&s2,  g_sum2);
    cudaGetSymbolAddress((void**)&q2,  g_ss2);
    cudaGetSymbolAddress((void**)&s3,  g_sum3);
    cudaGetSymbolAddress((void**)&q3,  g_ss3);

    const int SMEM = (3 * IN_SZ + 3 * WF_SZ + 128) * 4;  // 125696 B
    cudaFuncSetAttribute(convmma_k<64, 512, 512, true>,
                         cudaFuncAttributeMaxDynamicSharedMemorySize, SMEM);
    cudaFuncSetAttribute(convmma_k<256, 256, 256, false>,
                         cudaFuncAttributeMaxDynamicSharedMemorySize, SMEM);

    // 1: conv1 (+ zero all stats)
    conv1_k<<<4096, 256>>>(inp, w1, x1, s1, q1, s2, q2, s3, q3);
    // 2: BN1 stats
    stats_k<<<dim3(64, 32), 256>>>(x1, 512 * 512, s1, q1);
    // 3: fold BN1 into conv2 weights + border table
    prep2_k<<<64, 256>>>(w2, pg1, pbe1, s1, q1, w2p, Tt);
    // 4: conv2  <- ncu profiles launch #4
    convmma_k<64, 512, 512, true><<<dim3(16, 32, 4), 512, SMEM>>>(
        x1, w2p, Tt, s2, q2, x2);
    // 5: conv3 weight prep
    prep3_k<<<64, 256>>>(w3, w3p);
    // 6: skip = relu(BN2(x2)); dwt = Haar(skip)
    dwt_k<<<32768, 256>>>(x2, pg2, pbe2, s2, q2, skip, dwt);
    // 7: conv3
    convmma_k<256, 256, 256, false><<<dim3(8, 16, 4), 512, SMEM>>>(
        dwt, w3p, nullptr, s3, q3, y3);
    // 8: dwt_out = relu(BN3(y3))
    bn3relu_k<<<65536, 256>>>(y3, pg3, pbe3, s3, q3, dwt_out);
}